// round 1
// baseline (speedup 1.0000x reference)
#include <cuda_runtime.h>
#include <math.h>

#define NSP   10000
#define NLOC  50000
#define EOBS  500000
#define ENEAR 400000
#define HID   128
#define HEADS 4
#define CH    32

// ---------------- scratch (static device globals; no allocation) ----------------
__device__ float g_hsp  [NSP  * HID];
__device__ float g_hloc [NLOC * HID];
__device__ float g_Ploc [NLOC * HID];
__device__ float g_Psp  [NSP  * HID];
__device__ float g_newsp [NSP  * HID];
__device__ float g_newloc[NLOC * HID];
__device__ float g_als [NLOC * HEADS];
__device__ float g_ald [NLOC * HEADS];
__device__ float g_emax[NLOC * HEADS];
__device__ float g_den [NLOC * HEADS];

// ---------------- device helpers ----------------
__device__ __forceinline__ float lrelu(float x) { return x > 0.f ? x : 0.2f * x; }

__device__ __forceinline__ void atomicMaxF(float* addr, float v) {
    if (v >= 0.f) atomicMax((int*)addr, __float_as_int(v));
    else          atomicMin((unsigned int*)addr, __float_as_uint(v));
}

// ---------------- GEMM: C[M,128] = A[M,128] @ W[128,128] ----------------
__global__ void gemm128_kernel(const float* __restrict__ A, const float* __restrict__ W,
                               float* __restrict__ C, int M) {
    __shared__ float As[16][128];
    int row0 = blockIdx.x * 16;
    int j = threadIdx.x;
    #pragma unroll
    for (int r = 0; r < 16; ++r) {
        int m = row0 + r;
        As[r][j] = (m < M) ? A[(size_t)m * HID + j] : 0.f;
    }
    __syncthreads();
    float acc[16];
    #pragma unroll
    for (int r = 0; r < 16; ++r) acc[r] = 0.f;
    const float4* As4 = (const float4*)&As[0][0];
    #pragma unroll 4
    for (int k4 = 0; k4 < 32; ++k4) {
        int k = k4 * 4;
        float w0 = W[(k + 0) * HID + j];
        float w1 = W[(k + 1) * HID + j];
        float w2 = W[(k + 2) * HID + j];
        float w3 = W[(k + 3) * HID + j];
        #pragma unroll
        for (int r = 0; r < 16; ++r) {
            float4 a = As4[r * 32 + k4];
            acc[r] += a.x * w0;
            acc[r] += a.y * w1;
            acc[r] += a.z * w2;
            acc[r] += a.w * w3;
        }
    }
    #pragma unroll
    for (int r = 0; r < 16; ++r) {
        int m = row0 + r;
        if (m < M) C[(size_t)m * HID + j] = acc[r];
    }
}

// ---------------- input features: C[M,128] = A[M,64] @ W[64,128] + b ----------------
__global__ void gemm64_kernel(const float* __restrict__ A, const float* __restrict__ W,
                              const float* __restrict__ b, float* __restrict__ C, int M) {
    __shared__ float As[16][64];
    int row0 = blockIdx.x * 16;
    int j = threadIdx.x;
    for (int i = j; i < 16 * 64; i += 128) {
        int r = i >> 6, k = i & 63;
        int m = row0 + r;
        As[r][k] = (m < M) ? A[(size_t)m * 64 + k] : 0.f;
    }
    __syncthreads();
    float acc[16];
    #pragma unroll
    for (int r = 0; r < 16; ++r) acc[r] = 0.f;
    const float4* As4 = (const float4*)&As[0][0];
    #pragma unroll 4
    for (int k4 = 0; k4 < 16; ++k4) {
        int k = k4 * 4;
        float w0 = W[(k + 0) * HID + j];
        float w1 = W[(k + 1) * HID + j];
        float w2 = W[(k + 2) * HID + j];
        float w3 = W[(k + 3) * HID + j];
        #pragma unroll
        for (int r = 0; r < 16; ++r) {
            float4 a = As4[r * 16 + k4];
            acc[r] += a.x * w0;
            acc[r] += a.y * w1;
            acc[r] += a.z * w2;
            acc[r] += a.w * w3;
        }
    }
    float bj = b[j];
    #pragma unroll
    for (int r = 0; r < 16; ++r) {
        int m = row0 + r;
        if (m < M) C[(size_t)m * HID + j] = acc[r] + bj;
    }
}

// species features: A[m,k] = k<48 ? emb[sp_idx[m]][k] : grp[m][k-48]
__global__ void feat_sp_kernel(const int* __restrict__ sp_idx,
                               const float* __restrict__ emb, const float* __restrict__ grp,
                               const float* __restrict__ W, const float* __restrict__ b,
                               float* __restrict__ C) {
    __shared__ float As[16][64];
    int row0 = blockIdx.x * 16;
    int j = threadIdx.x;
    for (int i = j; i < 16 * 64; i += 128) {
        int r = i >> 6, k = i & 63;
        int m = row0 + r;
        float v = 0.f;
        if (m < NSP) {
            if (k < 48) v = emb[(size_t)sp_idx[m] * 48 + k];
            else        v = grp[(size_t)m * 16 + (k - 48)];
        }
        As[r][k] = v;
    }
    __syncthreads();
    float acc[16];
    #pragma unroll
    for (int r = 0; r < 16; ++r) acc[r] = 0.f;
    const float4* As4 = (const float4*)&As[0][0];
    #pragma unroll 4
    for (int k4 = 0; k4 < 16; ++k4) {
        int k = k4 * 4;
        float w0 = W[(k + 0) * HID + j];
        float w1 = W[(k + 1) * HID + j];
        float w2 = W[(k + 2) * HID + j];
        float w3 = W[(k + 3) * HID + j];
        #pragma unroll
        for (int r = 0; r < 16; ++r) {
            float4 a = As4[r * 16 + k4];
            acc[r] += a.x * w0;
            acc[r] += a.y * w1;
            acc[r] += a.z * w2;
            acc[r] += a.w * w3;
        }
    }
    float bj = b[j];
    #pragma unroll
    for (int r = 0; r < 16; ++r) {
        int m = row0 + r;
        if (m < NSP) C[(size_t)m * HID + j] = acc[r] + bj;
    }
}

// ---------------- attention logits: al[n,h] = sum_c P[n,h*32+c]*a[h*32+c] ----------------
__global__ void al_kernel(const float* __restrict__ P, const float* __restrict__ a,
                          float* __restrict__ al, int N) {
    int t = blockIdx.x * blockDim.x + threadIdx.x;
    if (t >= N * 4) return;
    int n = t >> 2, h = t & 3;
    const float4* p  = (const float4*)(P + (size_t)n * HID + h * CH);
    const float4* av = (const float4*)(a + h * CH);
    float s = 0.f;
    #pragma unroll
    for (int i = 0; i < 8; ++i) {
        float4 x = p[i], y = av[i];
        s += x.x * y.x + x.y * y.y + x.z * y.z + x.w * y.w;
    }
    al[t] = s;
}

// ---------------- fills ----------------
__global__ void fill_kernel(float* __restrict__ p, float v, int n) {
    int i = blockIdx.x * blockDim.x + threadIdx.x;
    if (i < n) p[i] = v;
}

__global__ void init_bias_kernel(float* __restrict__ out, const float* __restrict__ b0,
                                 const float* __restrict__ b1, int total) {
    int i = blockIdx.x * blockDim.x + threadIdx.x;
    if (i >= total) return;
    float v = b0[i & 127];
    if (b1) v += b1[i & 127];
    out[i] = v;
}

// ---------------- edge passes ----------------
// layout: ei[e] = src, ei[E + e] = dst; edges e in [E, Etot) are self-loops (i,i), i = e-E
__global__ void edge_max_kernel(const int* __restrict__ ei, int E, int Etot,
                                const float* __restrict__ als, const float* __restrict__ ald,
                                float* __restrict__ emax) {
    int e = blockIdx.x * blockDim.x + threadIdx.x;
    if (e >= Etot) return;
    int src, dst;
    if (e < E) { src = ei[e]; dst = ei[E + e]; } else { src = dst = e - E; }
    float4 s = ((const float4*)als)[src];
    float4 d = ((const float4*)ald)[dst];
    float v0 = lrelu(s.x + d.x);
    float v1 = lrelu(s.y + d.y);
    float v2 = lrelu(s.z + d.z);
    float v3 = lrelu(s.w + d.w);
    float* em = emax + (size_t)dst * 4;
    atomicMaxF(em + 0, v0);
    atomicMaxF(em + 1, v1);
    atomicMaxF(em + 2, v2);
    atomicMaxF(em + 3, v3);
}

__global__ void edge_den_kernel(const int* __restrict__ ei, int E, int Etot,
                                const float* __restrict__ als, const float* __restrict__ ald,
                                const float* __restrict__ emax, float* __restrict__ den) {
    int e = blockIdx.x * blockDim.x + threadIdx.x;
    if (e >= Etot) return;
    int src, dst;
    if (e < E) { src = ei[e]; dst = ei[E + e]; } else { src = dst = e - E; }
    float4 s = ((const float4*)als)[src];
    float4 d = ((const float4*)ald)[dst];
    float4 m = ((const float4*)emax)[dst];
    float e0 = __expf(lrelu(s.x + d.x) - m.x);
    float e1 = __expf(lrelu(s.y + d.y) - m.y);
    float e2 = __expf(lrelu(s.z + d.z) - m.z);
    float e3 = __expf(lrelu(s.w + d.w) - m.w);
    float* dn = den + (size_t)dst * 4;
    atomicAdd(dn + 0, e0);
    atomicAdd(dn + 1, e1);
    atomicAdd(dn + 2, e2);
    atomicAdd(dn + 3, e3);
}

// one warp per edge: lane covers 4 consecutive output channels
__global__ void edge_aggr_kernel(const int* __restrict__ ei, int E, int Etot,
                                 const float* __restrict__ als, const float* __restrict__ ald,
                                 const float* __restrict__ emax, const float* __restrict__ den,
                                 const float* __restrict__ Psrc, float* __restrict__ out) {
    int gt = blockIdx.x * blockDim.x + threadIdx.x;
    int e = gt >> 5;
    if (e >= Etot) return;
    int lane = threadIdx.x & 31;
    int src, dst;
    if (e < E) { src = ei[e]; dst = ei[E + e]; } else { src = dst = e - E; }
    int h = lane >> 3;
    float v = als[src * 4 + h] + ald[dst * 4 + h];
    v = lrelu(v);
    float alpha = __expf(v - emax[dst * 4 + h]) / (den[dst * 4 + h] + 1e-16f);
    float4 x = ((const float4*)Psrc)[src * 32 + lane];
    float* o = out + (size_t)dst * HID + lane * 4;
    atomicAdd(o + 0, alpha * x.x);
    atomicAdd(o + 1, alpha * x.y);
    atomicAdd(o + 2, alpha * x.z);
    atomicAdd(o + 3, alpha * x.w);
}

// ---------------- combines ----------------
__global__ void add_relu_kernel(float* __restrict__ h, const float* __restrict__ nw, int n) {
    int i = blockIdx.x * blockDim.x + threadIdx.x;
    if (i < n) {
        float v = h[i] + nw[i];
        h[i] = v > 0.f ? v : 0.f;
    }
}

__global__ void add_out_kernel(float* __restrict__ o, const float* __restrict__ h,
                               const float* __restrict__ nw, int n) {
    int i = blockIdx.x * blockDim.x + threadIdx.x;
    if (i < n) o[i] = h[i] + nw[i];
}

// ---------------- host ----------------
static float* symaddr(const void* sym) {
    void* p = nullptr;
    cudaGetSymbolAddress(&p, sym);
    return (float*)p;
}

static void run_relation(const float* hsrc, int Nsrc, float* Psrc,
                         const float* hdst, int Ndst, float* Pdst,
                         const float* W, const float* a_s, const float* a_d,
                         const int* ei, int E, int Etot,
                         float* als, float* ald, float* emax, float* den,
                         float* out) {
    gemm128_kernel<<<(Nsrc + 15) / 16, 128>>>(hsrc, W, Psrc, Nsrc);
    if (Pdst != Psrc)
        gemm128_kernel<<<(Ndst + 15) / 16, 128>>>(hdst, W, Pdst, Ndst);
    al_kernel<<<(Nsrc * 4 + 255) / 256, 256>>>(Psrc, a_s, als, Nsrc);
    al_kernel<<<(Ndst * 4 + 255) / 256, 256>>>(Pdst, a_d, ald, Ndst);
    fill_kernel<<<(Ndst * 4 + 255) / 256, 256>>>(emax, -INFINITY, Ndst * 4);
    fill_kernel<<<(Ndst * 4 + 255) / 256, 256>>>(den, 0.f, Ndst * 4);
    edge_max_kernel<<<(Etot + 255) / 256, 256>>>(ei, E, Etot, als, ald, emax);
    edge_den_kernel<<<(Etot + 255) / 256, 256>>>(ei, E, Etot, als, ald, emax, den);
    long long threads = (long long)Etot * 32;
    edge_aggr_kernel<<<(unsigned)((threads + 255) / 256), 256>>>(ei, E, Etot, als, ald, emax,
                                                                 den, Psrc, out);
}

extern "C" void kernel_launch(void* const* d_in, const int* in_sizes, int n_in,
                              void* d_out, int out_size) {
    const int*   sp_idx = (const int*)  d_in[0];
    const float* grp    = (const float*)d_in[1];
    const float* locx   = (const float*)d_in[2];
    const int*   ei_obs   = (const int*)d_in[3];
    const int*   ei_obsat = (const int*)d_in[4];
    const int*   ei_near  = (const int*)d_in[5];
    const float* emb    = (const float*)d_in[6];
    const float* spw    = (const float*)d_in[7];
    const float* spb    = (const float*)d_in[8];
    const float* locw   = (const float*)d_in[9];
    const float* locb   = (const float*)d_in[10];
    const float* gatw   = (const float*)d_in[11];
    const float* gatas  = (const float*)d_in[12];
    const float* gatad  = (const float*)d_in[13];
    const float* gatb   = (const float*)d_in[14];
    float* out = (float*)d_out;

    float* hsp   = symaddr(g_hsp);
    float* hloc  = symaddr(g_hloc);
    float* Ploc  = symaddr(g_Ploc);
    float* Psp   = symaddr(g_Psp);
    float* newsp = symaddr(g_newsp);
    float* newloc= symaddr(g_newloc);
    float* als   = symaddr(g_als);
    float* ald   = symaddr(g_ald);
    float* emax  = symaddr(g_emax);
    float* den   = symaddr(g_den);

    // input features
    feat_sp_kernel<<<(NSP + 15) / 16, 128>>>(sp_idx, emb, grp, spw, spb, hsp);
    gemm64_kernel<<<(NLOC + 15) / 16, 128>>>(locx, locw, locb, hloc, NLOC);

    for (int l = 0; l < 2; ++l) {
        const float* Wl  = gatw  + (size_t)l * 3 * HID * HID;
        const float* asl = gatas + (size_t)l * 3 * HID;
        const float* adl = gatad + (size_t)l * 3 * HID;
        const float* bl  = gatb  + (size_t)l * 3 * HID;

        init_bias_kernel<<<(NSP * HID + 255) / 256, 256>>>(newsp, bl, nullptr, NSP * HID);
        init_bias_kernel<<<(NLOC * HID + 255) / 256, 256>>>(newloc, bl + HID, bl + 2 * HID,
                                                            NLOC * HID);

        // r0: observes (loc -> sp)
        run_relation(hloc, NLOC, Ploc, hsp, NSP, Psp,
                     Wl, asl, adl,
                     ei_obs, EOBS, EOBS, als, ald, emax, den, newsp);
        // r1: observed_at (sp -> loc)
        run_relation(hsp, NSP, Psp, hloc, NLOC, Ploc,
                     Wl + HID * HID, asl + HID, adl + HID,
                     ei_obsat, EOBS, EOBS, als, ald, emax, den, newloc);
        // r2: nearby (loc -> loc) + self loops
        run_relation(hloc, NLOC, Ploc, hloc, NLOC, Ploc,
                     Wl + 2 * HID * HID, asl + 2 * HID, adl + 2 * HID,
                     ei_near, ENEAR, ENEAR + NLOC, als, ald, emax, den, newloc);

        if (l == 0) {
            add_relu_kernel<<<(NSP * HID + 255) / 256, 256>>>(hsp, newsp, NSP * HID);
            add_relu_kernel<<<(NLOC * HID + 255) / 256, 256>>>(hloc, newloc, NLOC * HID);
        } else {
            add_out_kernel<<<(NSP * HID + 255) / 256, 256>>>(out, hsp, newsp, NSP * HID);
            add_out_kernel<<<(NLOC * HID + 255) / 256, 256>>>(out + (size_t)NSP * HID, hloc,
                                                              newloc, NLOC * HID);
        }
    }
}

// round 2
// speedup vs baseline: 1.9886x; 1.9886x over previous
#include <cuda_runtime.h>
#include <math.h>

#define NSP   10000
#define NLOC  50000
#define EOBS  500000
#define ENEAR 400000
#define HID   128
#define HEADS 4
#define CH    32

// ---------------- scratch (static device globals) ----------------
__device__ float g_hsp  [NSP  * HID];
__device__ float g_hloc [NLOC * HID];
__device__ float g_PlocA[NLOC * HID];   // hloc @ W0 (src proj for 'observes')
__device__ float g_PlocC[NLOC * HID];   // hloc @ W2 (src proj for 'nearby')
__device__ float g_PspB [NSP  * HID];   // hsp  @ W1 (src proj for 'observed_at')
__device__ float g_tmpsp [NSP  * HID];
__device__ float g_tmploc[NLOC * HID];
__device__ float g_als0[NLOC * HEADS];
__device__ float g_ald0[NSP  * HEADS];
__device__ float g_als1[NSP  * HEADS];
__device__ float g_ald1[NLOC * HEADS];
__device__ float g_als2[NLOC * HEADS];
__device__ float g_ald2[NLOC * HEADS];
__device__ float g_wd  [2 * HEADS * HID];    // W@a_d for r0, r1

// CSR scratch
__device__ int g_rp_obs  [NSP + 1];
__device__ int g_rp_obsat[NLOC + 1];
__device__ int g_rp_near [NLOC + 1];
__device__ int g_cur_obs  [NSP];
__device__ int g_cur_obsat[NLOC];
__device__ int g_cur_near [NLOC];
__device__ int g_deg_obs  [NSP];
__device__ int g_deg_obsat[NLOC];
__device__ int g_deg_near [NLOC];
__device__ int g_csrc_obs  [EOBS];
__device__ int g_csrc_obsat[EOBS];
__device__ int g_csrc_near [ENEAR];

__device__ __forceinline__ float lrelu(float x) { return x > 0.f ? x : 0.2f * x; }

// ---------------- GEMM: C[M,128] = A[M,128] @ W[128,128] ----------------
__global__ void gemm128_kernel(const float* __restrict__ A, const float* __restrict__ W,
                               float* __restrict__ C, int M) {
    __shared__ float As[16][128];
    int row0 = blockIdx.x * 16;
    int j = threadIdx.x;
    #pragma unroll
    for (int r = 0; r < 16; ++r) {
        int m = row0 + r;
        As[r][j] = (m < M) ? A[(size_t)m * HID + j] : 0.f;
    }
    __syncthreads();
    float acc[16];
    #pragma unroll
    for (int r = 0; r < 16; ++r) acc[r] = 0.f;
    const float4* As4 = (const float4*)&As[0][0];
    #pragma unroll 4
    for (int k4 = 0; k4 < 32; ++k4) {
        int k = k4 * 4;
        float w0 = W[(k + 0) * HID + j];
        float w1 = W[(k + 1) * HID + j];
        float w2 = W[(k + 2) * HID + j];
        float w3 = W[(k + 3) * HID + j];
        #pragma unroll
        for (int r = 0; r < 16; ++r) {
            float4 a = As4[r * 32 + k4];
            acc[r] += a.x * w0;
            acc[r] += a.y * w1;
            acc[r] += a.z * w2;
            acc[r] += a.w * w3;
        }
    }
    #pragma unroll
    for (int r = 0; r < 16; ++r) {
        int m = row0 + r;
        if (m < M) C[(size_t)m * HID + j] = acc[r];
    }
}

// ---------------- input features ----------------
__global__ void gemm64_kernel(const float* __restrict__ A, const float* __restrict__ W,
                              const float* __restrict__ b, float* __restrict__ C, int M) {
    __shared__ float As[16][64];
    int row0 = blockIdx.x * 16;
    int j = threadIdx.x;
    for (int i = j; i < 16 * 64; i += 128) {
        int r = i >> 6, k = i & 63;
        int m = row0 + r;
        As[r][k] = (m < M) ? A[(size_t)m * 64 + k] : 0.f;
    }
    __syncthreads();
    float acc[16];
    #pragma unroll
    for (int r = 0; r < 16; ++r) acc[r] = 0.f;
    const float4* As4 = (const float4*)&As[0][0];
    #pragma unroll 4
    for (int k4 = 0; k4 < 16; ++k4) {
        int k = k4 * 4;
        float w0 = W[(k + 0) * HID + j];
        float w1 = W[(k + 1) * HID + j];
        float w2 = W[(k + 2) * HID + j];
        float w3 = W[(k + 3) * HID + j];
        #pragma unroll
        for (int r = 0; r < 16; ++r) {
            float4 a = As4[r * 16 + k4];
            acc[r] += a.x * w0;
            acc[r] += a.y * w1;
            acc[r] += a.z * w2;
            acc[r] += a.w * w3;
        }
    }
    float bj = b[j];
    #pragma unroll
    for (int r = 0; r < 16; ++r) {
        int m = row0 + r;
        if (m < M) C[(size_t)m * HID + j] = acc[r] + bj;
    }
}

__global__ void feat_sp_kernel(const int* __restrict__ sp_idx,
                               const float* __restrict__ emb, const float* __restrict__ grp,
                               const float* __restrict__ W, const float* __restrict__ b,
                               float* __restrict__ C) {
    __shared__ float As[16][64];
    int row0 = blockIdx.x * 16;
    int j = threadIdx.x;
    for (int i = j; i < 16 * 64; i += 128) {
        int r = i >> 6, k = i & 63;
        int m = row0 + r;
        float v = 0.f;
        if (m < NSP) {
            if (k < 48) v = emb[(size_t)sp_idx[m] * 48 + k];
            else        v = grp[(size_t)m * 16 + (k - 48)];
        }
        As[r][k] = v;
    }
    __syncthreads();
    float acc[16];
    #pragma unroll
    for (int r = 0; r < 16; ++r) acc[r] = 0.f;
    const float4* As4 = (const float4*)&As[0][0];
    #pragma unroll 4
    for (int k4 = 0; k4 < 16; ++k4) {
        int k = k4 * 4;
        float w0 = W[(k + 0) * HID + j];
        float w1 = W[(k + 1) * HID + j];
        float w2 = W[(k + 2) * HID + j];
        float w3 = W[(k + 3) * HID + j];
        #pragma unroll
        for (int r = 0; r < 16; ++r) {
            float4 a = As4[r * 16 + k4];
            acc[r] += a.x * w0;
            acc[r] += a.y * w1;
            acc[r] += a.z * w2;
            acc[r] += a.w * w3;
        }
    }
    float bj = b[j];
    #pragma unroll
    for (int r = 0; r < 16; ++r) {
        int m = row0 + r;
        if (m < NSP) C[(size_t)m * HID + j] = acc[r] + bj;
    }
}

// ---------------- al[n,h] = sum_c P[n,h*32+c]*a[h*32+c] ----------------
__global__ void al_kernel(const float* __restrict__ P, const float* __restrict__ a,
                          float* __restrict__ al, int N) {
    int t = blockIdx.x * blockDim.x + threadIdx.x;
    if (t >= N * 4) return;
    int n = t >> 2, h = t & 3;
    const float4* p  = (const float4*)(P + (size_t)n * HID + h * CH);
    const float4* av = (const float4*)(a + h * CH);
    float s = 0.f;
    #pragma unroll
    for (int i = 0; i < 8; ++i) {
        float4 x = p[i], y = av[i];
        s += x.x * y.x + x.y * y.y + x.z * y.z + x.w * y.w;
    }
    al[t] = s;
}

// ---------------- wd[rel][h][k] = sum_c W_rel[k, h*32+c] * a_d[rel][h][c] ----------------
__global__ void wd_kernel(const float* __restrict__ W0, const float* __restrict__ ad0,
                          const float* __restrict__ W1, const float* __restrict__ ad1,
                          float* __restrict__ wd) {
    int t = blockIdx.x * blockDim.x + threadIdx.x;
    if (t >= 1024) return;
    int rel = t >> 9, rem = t & 511, h = rem >> 7, k = rem & 127;
    const float* W  = rel ? W1  : W0;
    const float* ad = rel ? ad1 : ad0;
    float s = 0.f;
    #pragma unroll
    for (int c = 0; c < 32; ++c) s += W[k * HID + h * CH + c] * ad[h * CH + c];
    wd[t] = s;
}

// ---------------- ald[n,h] = dot(hrow[n], wd[h]) (warp per node) ----------------
__global__ void ald_dot_kernel(const float* __restrict__ H, const float* __restrict__ wd,
                               float* __restrict__ ald, int N) {
    int w = (blockIdx.x * blockDim.x + threadIdx.x) >> 5;
    if (w >= N) return;
    int lane = threadIdx.x & 31;
    float4 hv = ((const float4*)H)[(size_t)w * 32 + lane];
    float r[4];
    #pragma unroll
    for (int hh = 0; hh < 4; ++hh) {
        float4 wv = ((const float4*)wd)[hh * 32 + lane];
        r[hh] = hv.x * wv.x + hv.y * wv.y + hv.z * wv.z + hv.w * wv.w;
    }
    #pragma unroll
    for (int off = 16; off; off >>= 1) {
        #pragma unroll
        for (int hh = 0; hh < 4; ++hh) r[hh] += __shfl_xor_sync(~0u, r[hh], off);
    }
    if (lane < 4) ald[(size_t)w * 4 + lane] = r[lane];
}

// ---------------- CSR build ----------------
__global__ void filli_kernel(int* __restrict__ p, int v, int n) {
    int i = blockIdx.x * blockDim.x + threadIdx.x;
    if (i < n) p[i] = v;
}

__global__ void count_kernel(const int* __restrict__ ei, int E, int* __restrict__ deg) {
    int e = blockIdx.x * blockDim.x + threadIdx.x;
    if (e < E) atomicAdd(&deg[ei[E + e]], 1);
}

__global__ void scan_kernel(const int* __restrict__ deg, int* __restrict__ rowptr,
                            int* __restrict__ cursor, int n) {
    __shared__ int sh[1024];
    __shared__ int carry;
    if (threadIdx.x == 0) carry = 0;
    __syncthreads();
    for (int base = 0; base < n; base += 1024) {
        int i = base + (int)threadIdx.x;
        int v = (i < n) ? deg[i] : 0;
        sh[threadIdx.x] = v;
        __syncthreads();
        for (int off = 1; off < 1024; off <<= 1) {
            int t = (threadIdx.x >= off) ? sh[threadIdx.x - off] : 0;
            __syncthreads();
            sh[threadIdx.x] += t;
            __syncthreads();
        }
        int excl = sh[threadIdx.x] - v;
        if (i < n) {
            int o = carry + excl;
            rowptr[i] = o;
            cursor[i] = o;
        }
        __syncthreads();
        if (threadIdx.x == 1023) carry += sh[1023];
        __syncthreads();
    }
    if (threadIdx.x == 0) rowptr[n] = carry;
}

__global__ void scatter_kernel(const int* __restrict__ ei, int E,
                               int* __restrict__ cursor, int* __restrict__ csrc) {
    int e = blockIdx.x * blockDim.x + threadIdx.x;
    if (e >= E) return;
    int dst = ei[E + e];
    int pos = atomicAdd(&cursor[dst], 1);
    csrc[pos] = ei[e];
}

// ---------------- fused softmax + aggregate: warp per dst ----------------
// out[dst] = (sum_e ee_e * P[src_e]) / (sum_e ee_e),  ee = exp(lrelu(als[src]+ald[dst]))
__global__ void aggr_kernel(const int* __restrict__ rowptr, const int* __restrict__ csrc,
                            const float* __restrict__ als, const float* __restrict__ ald,
                            const float* __restrict__ P, float* __restrict__ out,
                            int Ndst, int accum, int selfloop) {
    int w = (blockIdx.x * blockDim.x + threadIdx.x) >> 5;
    if (w >= Ndst) return;
    int lane = threadIdx.x & 31;
    int h = lane >> 3;
    float ad = __ldg(ald + (size_t)w * 4 + h);
    float den = 0.f, ax = 0.f, ay = 0.f, az = 0.f, aw = 0.f;
    if (selfloop) {
        float ee = __expf(lrelu(__ldg(als + (size_t)w * 4 + h) + ad));
        den = ee;
        float4 x = __ldg((const float4*)P + (size_t)w * 32 + lane);
        ax = ee * x.x; ay = ee * x.y; az = ee * x.z; aw = ee * x.w;
    }
    int i = __ldg(rowptr + w), end = __ldg(rowptr + w + 1);
    for (; i + 4 <= end; i += 4) {
        int s0 = __ldg(csrc + i + 0);
        int s1 = __ldg(csrc + i + 1);
        int s2 = __ldg(csrc + i + 2);
        int s3 = __ldg(csrc + i + 3);
        float e0 = lrelu(__ldg(als + (size_t)s0 * 4 + h) + ad);
        float e1 = lrelu(__ldg(als + (size_t)s1 * 4 + h) + ad);
        float e2 = lrelu(__ldg(als + (size_t)s2 * 4 + h) + ad);
        float e3 = lrelu(__ldg(als + (size_t)s3 * 4 + h) + ad);
        float4 x0 = __ldg((const float4*)P + (size_t)s0 * 32 + lane);
        float4 x1 = __ldg((const float4*)P + (size_t)s1 * 32 + lane);
        float4 x2 = __ldg((const float4*)P + (size_t)s2 * 32 + lane);
        float4 x3 = __ldg((const float4*)P + (size_t)s3 * 32 + lane);
        float q0 = __expf(e0), q1 = __expf(e1), q2 = __expf(e2), q3 = __expf(e3);
        den += q0 + q1 + q2 + q3;
        ax += q0 * x0.x + q1 * x1.x + q2 * x2.x + q3 * x3.x;
        ay += q0 * x0.y + q1 * x1.y + q2 * x2.y + q3 * x3.y;
        az += q0 * x0.z + q1 * x1.z + q2 * x2.z + q3 * x3.z;
        aw += q0 * x0.w + q1 * x1.w + q2 * x2.w + q3 * x3.w;
    }
    for (; i < end; ++i) {
        int s = __ldg(csrc + i);
        float q = __expf(lrelu(__ldg(als + (size_t)s * 4 + h) + ad));
        float4 x = __ldg((const float4*)P + (size_t)s * 32 + lane);
        den += q;
        ax += q * x.x; ay += q * x.y; az += q * x.z; aw += q * x.w;
    }
    float inv = 1.f / (den + 1e-16f);
    float4 o = make_float4(ax * inv, ay * inv, az * inv, aw * inv);
    float4* op = (float4*)out + (size_t)w * 32 + lane;
    if (accum) {
        float4 p = *op;
        o.x += p.x; o.y += p.y; o.z += p.z; o.w += p.w;
    }
    *op = o;
}

// ---------------- combine ----------------
__global__ void combine_kernel(const float* __restrict__ h, const float* __restrict__ tmp,
                               const float* __restrict__ b, const float* __restrict__ b2,
                               float* __restrict__ out, int n, int do_relu) {
    int i = blockIdx.x * blockDim.x + threadIdx.x;
    if (i >= n) return;
    float v = h[i] + tmp[i] + b[i & 127];
    if (b2) v += b2[i & 127];
    if (do_relu) v = v > 0.f ? v : 0.f;
    out[i] = v;
}

// ---------------- host ----------------
static float* symaddrf(const void* sym) { void* p = nullptr; cudaGetSymbolAddress(&p, sym); return (float*)p; }
static int*   symaddri(const void* sym) { void* p = nullptr; cudaGetSymbolAddress(&p, sym); return (int*)p; }

static void build_csr(const int* ei, int E, int N, int* deg, int* rowptr, int* cursor, int* csrc) {
    filli_kernel<<<(N + 255) / 256, 256>>>(deg, 0, N);
    count_kernel<<<(E + 255) / 256, 256>>>(ei, E, deg);
    scan_kernel<<<1, 1024>>>(deg, rowptr, cursor, N);
    scatter_kernel<<<(E + 255) / 256, 256>>>(ei, E, cursor, csrc);
}

extern "C" void kernel_launch(void* const* d_in, const int* in_sizes, int n_in,
                              void* d_out, int out_size) {
    const int*   sp_idx = (const int*)  d_in[0];
    const float* grp    = (const float*)d_in[1];
    const float* locx   = (const float*)d_in[2];
    const int*   ei_obs   = (const int*)d_in[3];
    const int*   ei_obsat = (const int*)d_in[4];
    const int*   ei_near  = (const int*)d_in[5];
    const float* emb    = (const float*)d_in[6];
    const float* spw    = (const float*)d_in[7];
    const float* spb    = (const float*)d_in[8];
    const float* locw   = (const float*)d_in[9];
    const float* locb   = (const float*)d_in[10];
    const float* gatw   = (const float*)d_in[11];
    const float* gatas  = (const float*)d_in[12];
    const float* gatad  = (const float*)d_in[13];
    const float* gatb   = (const float*)d_in[14];
    float* out = (float*)d_out;

    float* hsp   = symaddrf(g_hsp);
    float* hloc  = symaddrf(g_hloc);
    float* PlocA = symaddrf(g_PlocA);
    float* PlocC = symaddrf(g_PlocC);
    float* PspB  = symaddrf(g_PspB);
    float* tmpsp = symaddrf(g_tmpsp);
    float* tmploc= symaddrf(g_tmploc);
    float* als0  = symaddrf(g_als0);
    float* ald0  = symaddrf(g_ald0);
    float* als1  = symaddrf(g_als1);
    float* ald1  = symaddrf(g_ald1);
    float* als2  = symaddrf(g_als2);
    float* ald2  = symaddrf(g_ald2);
    float* wd    = symaddrf(g_wd);

    int* rp_obs   = symaddri(g_rp_obs);
    int* rp_obsat = symaddri(g_rp_obsat);
    int* rp_near  = symaddri(g_rp_near);
    int* cu_obs   = symaddri(g_cur_obs);
    int* cu_obsat = symaddri(g_cur_obsat);
    int* cu_near  = symaddri(g_cur_near);
    int* dg_obs   = symaddri(g_deg_obs);
    int* dg_obsat = symaddri(g_deg_obsat);
    int* dg_near  = symaddri(g_deg_near);
    int* cs_obs   = symaddri(g_csrc_obs);
    int* cs_obsat = symaddri(g_csrc_obsat);
    int* cs_near  = symaddri(g_csrc_near);

    // CSR build (once; reused for both layers)
    build_csr(ei_obs,   EOBS,  NSP,  dg_obs,   rp_obs,   cu_obs,   cs_obs);
    build_csr(ei_obsat, EOBS,  NLOC, dg_obsat, rp_obsat, cu_obsat, cs_obsat);
    build_csr(ei_near,  ENEAR, NLOC, dg_near,  rp_near,  cu_near,  cs_near);

    // input features
    feat_sp_kernel<<<(NSP + 15) / 16, 128>>>(sp_idx, emb, grp, spw, spb, hsp);
    gemm64_kernel<<<(NLOC + 15) / 16, 128>>>(locx, locw, locb, hloc, NLOC);

    for (int l = 0; l < 2; ++l) {
        const float* W0  = gatw  + (size_t)l * 3 * HID * HID;
        const float* W1  = W0 + HID * HID;
        const float* W2  = W0 + 2 * HID * HID;
        const float* as0 = gatas + (size_t)l * 3 * HID;
        const float* as1 = as0 + HID;
        const float* as2 = as0 + 2 * HID;
        const float* ad0 = gatad + (size_t)l * 3 * HID;
        const float* ad1 = ad0 + HID;
        const float* ad2 = ad0 + 2 * HID;
        const float* b0  = gatb  + (size_t)l * 3 * HID;
        const float* b1  = b0 + HID;
        const float* b2  = b0 + 2 * HID;

        // fold a_d into W for the two cross-type relations (skip dst projections)
        wd_kernel<<<4, 256>>>(W0, ad0, W1, ad1, wd);

        // src-side projections only
        gemm128_kernel<<<(NLOC + 15) / 16, 128>>>(hloc, W0, PlocA, NLOC);
        gemm128_kernel<<<(NSP  + 15) / 16, 128>>>(hsp,  W1, PspB,  NSP);
        gemm128_kernel<<<(NLOC + 15) / 16, 128>>>(hloc, W2, PlocC, NLOC);

        // attention logits
        al_kernel<<<(NLOC * 4 + 255) / 256, 256>>>(PlocA, as0, als0, NLOC);
        al_kernel<<<(NSP  * 4 + 255) / 256, 256>>>(PspB,  as1, als1, NSP);
        al_kernel<<<(NLOC * 4 + 255) / 256, 256>>>(PlocC, as2, als2, NLOC);
        al_kernel<<<(NLOC * 4 + 255) / 256, 256>>>(PlocC, ad2, ald2, NLOC);
        ald_dot_kernel<<<(NSP  * 32 + 255) / 256, 256>>>(hsp,  wd,       ald0, NSP);
        ald_dot_kernel<<<(NLOC * 32 + 255) / 256, 256>>>(hloc, wd + 512, ald1, NLOC);

        // fused softmax+aggregate (one edge pass per relation, no atomics)
        aggr_kernel<<<(NSP  * 32 + 255) / 256, 256>>>(rp_obs,   cs_obs,   als0, ald0,
                                                      PlocA, tmpsp,  NSP,  0, 0);
        aggr_kernel<<<(NLOC * 32 + 255) / 256, 256>>>(rp_obsat, cs_obsat, als1, ald1,
                                                      PspB,  tmploc, NLOC, 0, 0);
        aggr_kernel<<<(NLOC * 32 + 255) / 256, 256>>>(rp_near,  cs_near,  als2, ald2,
                                                      PlocC, tmploc, NLOC, 1, 1);

        // combine (+bias, +residual, relu for layer 0)
        if (l == 0) {
            combine_kernel<<<(NSP * HID + 255) / 256, 256>>>(hsp, tmpsp, b0, nullptr,
                                                             hsp, NSP * HID, 1);
            combine_kernel<<<(NLOC * HID + 255) / 256, 256>>>(hloc, tmploc, b1, b2,
                                                              hloc, NLOC * HID, 1);
        } else {
            combine_kernel<<<(NSP * HID + 255) / 256, 256>>>(hsp, tmpsp, b0, nullptr,
                                                             out, NSP * HID, 0);
            combine_kernel<<<(NLOC * HID + 255) / 256, 256>>>(hloc, tmploc, b1, b2,
                                                              out + (size_t)NSP * HID,
                                                              NLOC * HID, 0);
        }
    }
}

// round 5
// speedup vs baseline: 2.7380x; 1.3768x over previous
#include <cuda_runtime.h>
#include <math.h>
#include <stdint.h>

#define NSP   10000
#define NLOC  50000
#define EOBS  500000
#define ENEAR 400000
#define HID   128
#define HEADS 4
#define CH    32

// ---------------- scratch (static device globals) ----------------
__device__ float g_hsp  [NSP  * HID];
__device__ float g_hloc [NLOC * HID];
__device__ float g_PlocA[NLOC * HID];
__device__ float g_PlocC[NLOC * HID];
__device__ float g_PspB [NSP  * HID];
__device__ float g_tmpsp [NSP  * HID];
__device__ float g_tmploc[NLOC * HID];
__device__ float g_als0[NLOC * HEADS];
__device__ float g_ald0[NSP  * HEADS];
__device__ float g_als1[NSP  * HEADS];
__device__ float g_ald1[NLOC * HEADS];
__device__ float g_als2[NLOC * HEADS];
__device__ float g_ald2[NLOC * HEADS];
__device__ float g_wd  [2 * HEADS * HID];

// CSR scratch
__device__ int g_rp_obs  [NSP + 1];
__device__ int g_rp_obsat[NLOC + 1];
__device__ int g_rp_near [NLOC + 1];
__device__ int g_cur_obs  [NSP];
__device__ int g_cur_obsat[NLOC];
__device__ int g_cur_near [NLOC];
__device__ int g_deg_obs  [NSP];
__device__ int g_deg_obsat[NLOC];
__device__ int g_deg_near [NLOC];
__device__ int g_csrc_obs  [EOBS];
__device__ int g_csrc_obsat[EOBS];
__device__ int g_csrc_near [ENEAR];

__device__ __forceinline__ float lrelu(float x) { return x > 0.f ? x : 0.2f * x; }

__device__ __forceinline__ uint32_t f2tf32(float f) {
    uint32_t r;
    asm("cvt.rna.tf32.f32 %0, %1;" : "=r"(r) : "f"(f));
    return r;
}

// ---------------- tf32 tensor-core GEMM: C[M,128] = A[M,128] @ W[128,128] ----------------
// block = 256 threads (8 warps); each warp computes 16 rows x 128 cols.
// W staged in smem as tf32 in two 64-row K-chunks, rows padded to 136 (bank-conflict-free
// B-fragment loads: bank = (8k + n) % 32 covers all 32 banks within a warp).
#define WPAD 136
__global__ void __launch_bounds__(256)
gemm_tc_kernel(const float* __restrict__ A, const float* __restrict__ W,
               float* __restrict__ C, int M) {
    __shared__ uint32_t Ws[64 * WPAD];
    int warp = threadIdx.x >> 5, lane = threadIdx.x & 31;
    int gid = lane >> 2, tig = lane & 3;           // groupID, threadID_in_group
    int ra = blockIdx.x * 128 + warp * 16 + gid;   // row of a0/a2/c0/c1
    int rb = ra + 8;                                // row of a1/a3/c2/c3
    bool va = ra < M, vb = rb < M;
    const float* Aa = A + (size_t)(va ? ra : 0) * HID;
    const float* Ab = A + (size_t)(vb ? rb : 0) * HID;

    float c[16][4];
    #pragma unroll
    for (int t = 0; t < 16; ++t) { c[t][0] = c[t][1] = c[t][2] = c[t][3] = 0.f; }

    for (int kc = 0; kc < 2; ++kc) {               // two K-chunks of 64
        int kbase = kc * 64;
        __syncthreads();
        for (int i = threadIdx.x; i < 64 * 128; i += 256) {
            int k = i >> 7, n = i & 127;
            Ws[k * WPAD + n] = f2tf32(W[(size_t)(kbase + k) * HID + n]);
        }
        __syncthreads();
        #pragma unroll
        for (int k8 = 0; k8 < 8; ++k8) {
            int k0 = kbase + k8 * 8;               // absolute k for A
            int ks = k8 * 8;                       // smem-relative k
            uint32_t a0 = f2tf32(Aa[k0 + tig]);
            uint32_t a1 = f2tf32(Ab[k0 + tig]);
            uint32_t a2 = f2tf32(Aa[k0 + 4 + tig]);
            uint32_t a3 = f2tf32(Ab[k0 + 4 + tig]);
            const uint32_t* b0row = Ws + (ks + tig) * WPAD + gid;
            const uint32_t* b1row = Ws + (ks + 4 + tig) * WPAD + gid;
            #pragma unroll
            for (int t = 0; t < 16; ++t) {
                uint32_t b0 = b0row[t * 8];
                uint32_t b1 = b1row[t * 8];
                asm volatile(
                    "mma.sync.aligned.m16n8k8.row.col.f32.tf32.tf32.f32 "
                    "{%0,%1,%2,%3}, {%4,%5,%6,%7}, {%8,%9}, {%0,%1,%2,%3};"
                    : "+f"(c[t][0]), "+f"(c[t][1]), "+f"(c[t][2]), "+f"(c[t][3])
                    : "r"(a0), "r"(a1), "r"(a2), "r"(a3), "r"(b0), "r"(b1));
            }
        }
    }
    // epilogue: c0/c1 -> row ra, cols (t*8 + 2*tig, +1); c2/c3 -> row rb
    #pragma unroll
    for (int t = 0; t < 16; ++t) {
        int col = t * 8 + 2 * tig;
        if (va) *(float2*)(C + (size_t)ra * HID + col) = make_float2(c[t][0], c[t][1]);
        if (vb) *(float2*)(C + (size_t)rb * HID + col) = make_float2(c[t][2], c[t][3]);
    }
}

// ---------------- input features ----------------
__global__ void gemm64_kernel(const float* __restrict__ A, const float* __restrict__ W,
                              const float* __restrict__ b, float* __restrict__ C, int M) {
    __shared__ float As[16][64];
    int row0 = blockIdx.x * 16;
    int j = threadIdx.x;
    for (int i = j; i < 16 * 64; i += 128) {
        int r = i >> 6, k = i & 63;
        int m = row0 + r;
        As[r][k] = (m < M) ? A[(size_t)m * 64 + k] : 0.f;
    }
    __syncthreads();
    float acc[16];
    #pragma unroll
    for (int r = 0; r < 16; ++r) acc[r] = 0.f;
    const float4* As4 = (const float4*)&As[0][0];
    #pragma unroll 4
    for (int k4 = 0; k4 < 16; ++k4) {
        int k = k4 * 4;
        float w0 = W[(k + 0) * HID + j];
        float w1 = W[(k + 1) * HID + j];
        float w2 = W[(k + 2) * HID + j];
        float w3 = W[(k + 3) * HID + j];
        #pragma unroll
        for (int r = 0; r < 16; ++r) {
            float4 a = As4[r * 16 + k4];
            acc[r] += a.x * w0;
            acc[r] += a.y * w1;
            acc[r] += a.z * w2;
            acc[r] += a.w * w3;
        }
    }
    float bj = b[j];
    #pragma unroll
    for (int r = 0; r < 16; ++r) {
        int m = row0 + r;
        if (m < M) C[(size_t)m * HID + j] = acc[r] + bj;
    }
}

__global__ void feat_sp_kernel(const int* __restrict__ sp_idx,
                               const float* __restrict__ emb, const float* __restrict__ grp,
                               const float* __restrict__ W, const float* __restrict__ b,
                               float* __restrict__ C) {
    __shared__ float As[16][64];
    int row0 = blockIdx.x * 16;
    int j = threadIdx.x;
    for (int i = j; i < 16 * 64; i += 128) {
        int r = i >> 6, k = i & 63;
        int m = row0 + r;
        float v = 0.f;
        if (m < NSP) {
            if (k < 48) v = emb[(size_t)sp_idx[m] * 48 + k];
            else        v = grp[(size_t)m * 16 + (k - 48)];
        }
        As[r][k] = v;
    }
    __syncthreads();
    float acc[16];
    #pragma unroll
    for (int r = 0; r < 16; ++r) acc[r] = 0.f;
    const float4* As4 = (const float4*)&As[0][0];
    #pragma unroll 4
    for (int k4 = 0; k4 < 16; ++k4) {
        int k = k4 * 4;
        float w0 = W[(k + 0) * HID + j];
        float w1 = W[(k + 1) * HID + j];
        float w2 = W[(k + 2) * HID + j];
        float w3 = W[(k + 3) * HID + j];
        #pragma unroll
        for (int r = 0; r < 16; ++r) {
            float4 a = As4[r * 16 + k4];
            acc[r] += a.x * w0;
            acc[r] += a.y * w1;
            acc[r] += a.z * w2;
            acc[r] += a.w * w3;
        }
    }
    float bj = b[j];
    #pragma unroll
    for (int r = 0; r < 16; ++r) {
        int m = row0 + r;
        if (m < NSP) C[(size_t)m * HID + j] = acc[r] + bj;
    }
}

// ---------------- al[n,h] = sum_c P[n,h*32+c]*a[h*32+c] ----------------
__global__ void al_kernel(const float* __restrict__ P, const float* __restrict__ a,
                          float* __restrict__ al, int N) {
    int t = blockIdx.x * blockDim.x + threadIdx.x;
    if (t >= N * 4) return;
    int n = t >> 2, h = t & 3;
    const float4* p  = (const float4*)(P + (size_t)n * HID + h * CH);
    const float4* av = (const float4*)(a + h * CH);
    float s = 0.f;
    #pragma unroll
    for (int i = 0; i < 8; ++i) {
        float4 x = p[i], y = av[i];
        s += x.x * y.x + x.y * y.y + x.z * y.z + x.w * y.w;
    }
    al[t] = s;
}

// ---------------- wd[rel][h][k] = sum_c W_rel[k, h*32+c] * a_d[rel][h][c] ----------------
__global__ void wd_kernel(const float* __restrict__ W0, const float* __restrict__ ad0,
                          const float* __restrict__ W1, const float* __restrict__ ad1,
                          float* __restrict__ wd) {
    int t = blockIdx.x * blockDim.x + threadIdx.x;
    if (t >= 1024) return;
    int rel = t >> 9, rem = t & 511, h = rem >> 7, k = rem & 127;
    const float* W  = rel ? W1  : W0;
    const float* ad = rel ? ad1 : ad0;
    float s = 0.f;
    #pragma unroll
    for (int c = 0; c < 32; ++c) s += W[k * HID + h * CH + c] * ad[h * CH + c];
    wd[t] = s;
}

// ---------------- ald[n,h] = dot(hrow[n], wd[h]) (warp per node) ----------------
__global__ void ald_dot_kernel(const float* __restrict__ H, const float* __restrict__ wd,
                               float* __restrict__ ald, int N) {
    int w = (blockIdx.x * blockDim.x + threadIdx.x) >> 5;
    if (w >= N) return;
    int lane = threadIdx.x & 31;
    float4 hv = ((const float4*)H)[(size_t)w * 32 + lane];
    float r[4];
    #pragma unroll
    for (int hh = 0; hh < 4; ++hh) {
        float4 wv = ((const float4*)wd)[hh * 32 + lane];
        r[hh] = hv.x * wv.x + hv.y * wv.y + hv.z * wv.z + hv.w * wv.w;
    }
    #pragma unroll
    for (int off = 16; off; off >>= 1) {
        #pragma unroll
        for (int hh = 0; hh < 4; ++hh) r[hh] += __shfl_xor_sync(~0u, r[hh], off);
    }
    if (lane < 4) ald[(size_t)w * 4 + lane] = r[lane];
}

// ---------------- CSR build ----------------
__global__ void fill3_kernel(int* __restrict__ p0, int n0, int* __restrict__ p1, int n1,
                             int* __restrict__ p2, int n2) {
    int i = blockIdx.x * blockDim.x + threadIdx.x;
    if (i < n0) p0[i] = 0;
    if (i < n1) p1[i] = 0;
    if (i < n2) p2[i] = 0;
}

__global__ void count_kernel(const int* __restrict__ ei, int E, int* __restrict__ deg) {
    int e = blockIdx.x * blockDim.x + threadIdx.x;
    if (e < E) atomicAdd(&deg[ei[E + e]], 1);
}

__device__ void scan_one(const int* __restrict__ deg, int* __restrict__ rowptr,
                         int* __restrict__ cursor, int n, int* sh, int* carry_p) {
    if (threadIdx.x == 0) *carry_p = 0;
    __syncthreads();
    for (int base = 0; base < n; base += 1024) {
        int i = base + (int)threadIdx.x;
        int v = (i < n) ? deg[i] : 0;
        sh[threadIdx.x] = v;
        __syncthreads();
        for (int off = 1; off < 1024; off <<= 1) {
            int t = (threadIdx.x >= (unsigned)off) ? sh[threadIdx.x - off] : 0;
            __syncthreads();
            sh[threadIdx.x] += t;
            __syncthreads();
        }
        int excl = sh[threadIdx.x] - v;
        if (i < n) {
            int o = *carry_p + excl;
            rowptr[i] = o;
            cursor[i] = o;
        }
        __syncthreads();
        if (threadIdx.x == 1023) *carry_p += sh[1023];
        __syncthreads();
    }
    if (threadIdx.x == 0) rowptr[n] = *carry_p;
}

__global__ void scan3_kernel(const int* __restrict__ d0, int* __restrict__ r0, int* __restrict__ c0, int n0,
                             const int* __restrict__ d1, int* __restrict__ r1, int* __restrict__ c1, int n1,
                             const int* __restrict__ d2, int* __restrict__ r2, int* __restrict__ c2, int n2) {
    __shared__ int sh[1024];
    __shared__ int carry;
    if (blockIdx.x == 0)      scan_one(d0, r0, c0, n0, sh, &carry);
    else if (blockIdx.x == 1) scan_one(d1, r1, c1, n1, sh, &carry);
    else                      scan_one(d2, r2, c2, n2, sh, &carry);
}

__global__ void scatter_kernel(const int* __restrict__ ei, int E,
                               int* __restrict__ cursor, int* __restrict__ csrc) {
    int e = blockIdx.x * blockDim.x + threadIdx.x;
    if (e >= E) return;
    int dst = ei[E + e];
    int pos = atomicAdd(&cursor[dst], 1);
    csrc[pos] = ei[e];
}

// ---------------- fused softmax + aggregate: warp per dst ----------------
__global__ void aggr_kernel(const int* __restrict__ rowptr, const int* __restrict__ csrc,
                            const float* __restrict__ als, const float* __restrict__ ald,
                            const float* __restrict__ P, float* __restrict__ out,
                            int Ndst, int accum, int selfloop) {
    int w = (blockIdx.x * blockDim.x + threadIdx.x) >> 5;
    if (w >= Ndst) return;
    int lane = threadIdx.x & 31;
    int h = lane >> 3;
    float ad = __ldg(ald + (size_t)w * 4 + h);
    float den = 0.f, ax = 0.f, ay = 0.f, az = 0.f, aw = 0.f;
    if (selfloop) {
        float ee = __expf(lrelu(__ldg(als + (size_t)w * 4 + h) + ad));
        den = ee;
        float4 x = __ldg((const float4*)P + (size_t)w * 32 + lane);
        ax = ee * x.x; ay = ee * x.y; az = ee * x.z; aw = ee * x.w;
    }
    int i = __ldg(rowptr + w), end = __ldg(rowptr + w + 1);
    for (; i + 4 <= end; i += 4) {
        int s0 = __ldg(csrc + i + 0);
        int s1 = __ldg(csrc + i + 1);
        int s2 = __ldg(csrc + i + 2);
        int s3 = __ldg(csrc + i + 3);
        float e0 = lrelu(__ldg(als + (size_t)s0 * 4 + h) + ad);
        float e1 = lrelu(__ldg(als + (size_t)s1 * 4 + h) + ad);
        float e2 = lrelu(__ldg(als + (size_t)s2 * 4 + h) + ad);
        float e3 = lrelu(__ldg(als + (size_t)s3 * 4 + h) + ad);
        float4 x0 = __ldg((const float4*)P + (size_t)s0 * 32 + lane);
        float4 x1 = __ldg((const float4*)P + (size_t)s1 * 32 + lane);
        float4 x2 = __ldg((const float4*)P + (size_t)s2 * 32 + lane);
        float4 x3 = __ldg((const float4*)P + (size_t)s3 * 32 + lane);
        float q0 = __expf(e0), q1 = __expf(e1), q2 = __expf(e2), q3 = __expf(e3);
        den += q0 + q1 + q2 + q3;
        ax += q0 * x0.x + q1 * x1.x + q2 * x2.x + q3 * x3.x;
        ay += q0 * x0.y + q1 * x1.y + q2 * x2.y + q3 * x3.y;
        az += q0 * x0.z + q1 * x1.z + q2 * x2.z + q3 * x3.z;
        aw += q0 * x0.w + q1 * x1.w + q2 * x2.w + q3 * x3.w;
    }
    for (; i < end; ++i) {
        int s = __ldg(csrc + i);
        float q = __expf(lrelu(__ldg(als + (size_t)s * 4 + h) + ad));
        float4 x = __ldg((const float4*)P + (size_t)s * 32 + lane);
        den += q;
        ax += q * x.x; ay += q * x.y; az += q * x.z; aw += q * x.w;
    }
    float inv = 1.f / (den + 1e-16f);
    float4 o = make_float4(ax * inv, ay * inv, az * inv, aw * inv);
    float4* op = (float4*)out + (size_t)w * 32 + lane;
    if (accum) {
        float4 p = *op;
        o.x += p.x; o.y += p.y; o.z += p.z; o.w += p.w;
    }
    *op = o;
}

// ---------------- combine ----------------
__global__ void combine_kernel(const float* __restrict__ h, const float* __restrict__ tmp,
                               const float* __restrict__ b, const float* __restrict__ b2,
                               float* __restrict__ out, int n, int do_relu) {
    int i = blockIdx.x * blockDim.x + threadIdx.x;
    if (i >= n) return;
    float v = h[i] + tmp[i] + b[i & 127];
    if (b2) v += b2[i & 127];
    if (do_relu) v = v > 0.f ? v : 0.f;
    out[i] = v;
}

// ---------------- host ----------------
static float* symaddrf(const void* sym) { void* p = nullptr; cudaGetSymbolAddress(&p, sym); return (float*)p; }
static int*   symaddri(const void* sym) { void* p = nullptr; cudaGetSymbolAddress(&p, sym); return (int*)p; }

extern "C" void kernel_launch(void* const* d_in, const int* in_sizes, int n_in,
                              void* d_out, int out_size) {
    const int*   sp_idx = (const int*)  d_in[0];
    const float* grp    = (const float*)d_in[1];
    const float* locx   = (const float*)d_in[2];
    const int*   ei_obs   = (const int*)d_in[3];
    const int*   ei_obsat = (const int*)d_in[4];
    const int*   ei_near  = (const int*)d_in[5];
    const float* emb    = (const float*)d_in[6];
    const float* spw    = (const float*)d_in[7];
    const float* spb    = (const float*)d_in[8];
    const float* locw   = (const float*)d_in[9];
    const float* locb   = (const float*)d_in[10];
    const float* gatw   = (const float*)d_in[11];
    const float* gatas  = (const float*)d_in[12];
    const float* gatad  = (const float*)d_in[13];
    const float* gatb   = (const float*)d_in[14];
    float* out = (float*)d_out;

    float* hsp   = symaddrf(g_hsp);
    float* hloc  = symaddrf(g_hloc);
    float* PlocA = symaddrf(g_PlocA);
    float* PlocC = symaddrf(g_PlocC);
    float* PspB  = symaddrf(g_PspB);
    float* tmpsp = symaddrf(g_tmpsp);
    float* tmploc= symaddrf(g_tmploc);
    float* als0  = symaddrf(g_als0);
    float* ald0  = symaddrf(g_ald0);
    float* als1  = symaddrf(g_als1);
    float* ald1  = symaddrf(g_ald1);
    float* als2  = symaddrf(g_als2);
    float* ald2  = symaddrf(g_ald2);
    float* wd    = symaddrf(g_wd);

    int* rp_obs   = symaddri(g_rp_obs);
    int* rp_obsat = symaddri(g_rp_obsat);
    int* rp_near  = symaddri(g_rp_near);
    int* cu_obs   = symaddri(g_cur_obs);
    int* cu_obsat = symaddri(g_cur_obsat);
    int* cu_near  = symaddri(g_cur_near);
    int* dg_obs   = symaddri(g_deg_obs);
    int* dg_obsat = symaddri(g_deg_obsat);
    int* dg_near  = symaddri(g_deg_near);
    int* cs_obs   = symaddri(g_csrc_obs);
    int* cs_obsat = symaddri(g_csrc_obsat);
    int* cs_near  = symaddri(g_csrc_near);

    // CSR build
    fill3_kernel<<<(NLOC + 255) / 256, 256>>>(dg_obs, NSP, dg_obsat, NLOC, dg_near, NLOC);
    count_kernel<<<(EOBS + 255) / 256, 256>>>(ei_obs, EOBS, dg_obs);
    count_kernel<<<(EOBS + 255) / 256, 256>>>(ei_obsat, EOBS, dg_obsat);
    count_kernel<<<(ENEAR + 255) / 256, 256>>>(ei_near, ENEAR, dg_near);
    scan3_kernel<<<3, 1024>>>(dg_obs, rp_obs, cu_obs, NSP,
                              dg_obsat, rp_obsat, cu_obsat, NLOC,
                              dg_near, rp_near, cu_near, NLOC);
    scatter_kernel<<<(EOBS + 255) / 256, 256>>>(ei_obs, EOBS, cu_obs, cs_obs);
    scatter_kernel<<<(EOBS + 255) / 256, 256>>>(ei_obsat, EOBS, cu_obsat, cs_obsat);
    scatter_kernel<<<(ENEAR + 255) / 256, 256>>>(ei_near, ENEAR, cu_near, cs_near);

    // input features
    feat_sp_kernel<<<(NSP + 15) / 16, 128>>>(sp_idx, emb, grp, spw, spb, hsp);
    gemm64_kernel<<<(NLOC + 15) / 16, 128>>>(locx, locw, locb, hloc, NLOC);

    for (int l = 0; l < 2; ++l) {
        const float* W0  = gatw  + (size_t)l * 3 * HID * HID;
        const float* W1  = W0 + HID * HID;
        const float* W2  = W0 + 2 * HID * HID;
        const float* as0 = gatas + (size_t)l * 3 * HID;
        const float* as1 = as0 + HID;
        const float* as2 = as0 + 2 * HID;
        const float* ad0 = gatad + (size_t)l * 3 * HID;
        const float* ad1 = ad0 + HID;
        const float* ad2 = ad0 + 2 * HID;
        const float* b0  = gatb  + (size_t)l * 3 * HID;
        const float* b1  = b0 + HID;
        const float* b2  = b0 + 2 * HID;

        wd_kernel<<<4, 256>>>(W0, ad0, W1, ad1, wd);

        // src-side projections (tf32 tensor cores)
        gemm_tc_kernel<<<(NLOC + 127) / 128, 256>>>(hloc, W0, PlocA, NLOC);
        gemm_tc_kernel<<<(NSP  + 127) / 128, 256>>>(hsp,  W1, PspB,  NSP);
        gemm_tc_kernel<<<(NLOC + 127) / 128, 256>>>(hloc, W2, PlocC, NLOC);

        // attention logits
        al_kernel<<<(NLOC * 4 + 255) / 256, 256>>>(PlocA, as0, als0, NLOC);
        al_kernel<<<(NSP  * 4 + 255) / 256, 256>>>(PspB,  as1, als1, NSP);
        al_kernel<<<(NLOC * 4 + 255) / 256, 256>>>(PlocC, as2, als2, NLOC);
        al_kernel<<<(NLOC * 4 + 255) / 256, 256>>>(PlocC, ad2, ald2, NLOC);
        ald_dot_kernel<<<(NSP  * 32 + 255) / 256, 256>>>(hsp,  wd,       ald0, NSP);
        ald_dot_kernel<<<(NLOC * 32 + 255) / 256, 256>>>(hloc, wd + 512, ald1, NLOC);

        // fused softmax+aggregate
        aggr_kernel<<<(NSP  * 32 + 255) / 256, 256>>>(rp_obs,   cs_obs,   als0, ald0,
                                                      PlocA, tmpsp,  NSP,  0, 0);
        aggr_kernel<<<(NLOC * 32 + 255) / 256, 256>>>(rp_obsat, cs_obsat, als1, ald1,
                                                      PspB,  tmploc, NLOC, 0, 0);
        aggr_kernel<<<(NLOC * 32 + 255) / 256, 256>>>(rp_near,  cs_near,  als2, ald2,
                                                      PlocC, tmploc, NLOC, 1, 1);

        if (l == 0) {
            combine_kernel<<<(NSP * HID + 255) / 256, 256>>>(hsp, tmpsp, b0, nullptr,
                                                             hsp, NSP * HID, 1);
            combine_kernel<<<(NLOC * HID + 255) / 256, 256>>>(hloc, tmploc, b1, b2,
                                                              hloc, NLOC * HID, 1);
        } else {
            combine_kernel<<<(NSP * HID + 255) / 256, 256>>>(hsp, tmpsp, b0, nullptr,
                                                             out, NSP * HID, 0);
            combine_kernel<<<(NLOC * HID + 255) / 256, 256>>>(hloc, tmploc, b1, b2,
                                                              out + (size_t)NSP * HID,
                                                              NLOC * HID, 0);
        }
    }
}

// round 6
// speedup vs baseline: 3.9611x; 1.4467x over previous
#include <cuda_runtime.h>
#include <math.h>
#include <stdint.h>

#define NSP   10000
#define NLOC  50000
#define EOBS  500000
#define ENEAR 400000
#define HID   128
#define HEADS 4
#define CH    32

// ---------------- scratch (static device globals) ----------------
__device__ float g_hsp  [NSP  * HID];
__device__ float g_hloc [NLOC * HID];
__device__ float g_PlocA[NLOC * HID];
__device__ float g_PlocC[NLOC * HID];
__device__ float g_PspB [NSP  * HID];
__device__ float g_als0[NLOC * HEADS];
__device__ float g_ald0[NSP  * HEADS];
__device__ float g_als1[NSP  * HEADS];
__device__ float g_ald1[NLOC * HEADS];
__device__ float g_als2[NLOC * HEADS];
__device__ float g_ald2[NLOC * HEADS];
__device__ float g_wd  [2 * 2 * HEADS * HID];   // [layer][rel(0=obs,1=obsat)][h][k]

// CSR scratch
__device__ int g_rp_obs  [NSP + 1];
__device__ int g_rp_obsat[NLOC + 1];
__device__ int g_rp_near [NLOC + 1];
__device__ int g_cur_obs  [NSP];
__device__ int g_cur_obsat[NLOC];
__device__ int g_cur_near [NLOC];
__device__ int g_deg_obs  [NSP];
__device__ int g_deg_obsat[NLOC];
__device__ int g_deg_near [NLOC];
__device__ int g_csrc_obs  [EOBS];
__device__ int g_csrc_obsat[EOBS];
__device__ int g_csrc_near [ENEAR];

__device__ __forceinline__ float lrelu(float x) { return x > 0.f ? x : 0.2f * x; }

__device__ __forceinline__ uint32_t f2tf32(float f) {
    uint32_t r;
    asm("cvt.rna.tf32.f32 %0, %1;" : "=r"(r) : "f"(f));
    return r;
}

// ---------------- tf32 GEMM + attention-logit epilogue ----------------
// grid.z selects relation: 0: hloc@W0->PlocA (+als0), 1: hsp@W1->PspB (+als1),
//                          2: hloc@W2->PlocC (+als2, +ald2)
#define WPAD 136
__global__ void __launch_bounds__(256)
gemm_tc_fused(const float* __restrict__ hsp, const float* __restrict__ hloc,
              const float* __restrict__ Wbase, const float* __restrict__ asbase,
              const float* __restrict__ ad2,
              float* __restrict__ PlocA, float* __restrict__ PspB, float* __restrict__ PlocC,
              float* __restrict__ als0, float* __restrict__ als1,
              float* __restrict__ als2, float* __restrict__ ald2o) {
    int rel = blockIdx.z;
    const float* A;  const float* W;  const float* avs;  const float* avd = nullptr;
    float* C;  float* als;  float* ald = nullptr;  int M;
    if (rel == 0)      { A = hloc; W = Wbase;                C = PlocA; M = NLOC; avs = asbase;           als = als0; }
    else if (rel == 1) { A = hsp;  W = Wbase + HID * HID;    C = PspB;  M = NSP;  avs = asbase + HID;     als = als1; }
    else               { A = hloc; W = Wbase + 2 * HID * HID;C = PlocC; M = NLOC; avs = asbase + 2 * HID; als = als2;
                         avd = ad2; ald = ald2o; }
    if (blockIdx.x * 128 >= M) return;

    __shared__ uint32_t Ws[64 * WPAD];
    int warp = threadIdx.x >> 5, lane = threadIdx.x & 31;
    int gid = lane >> 2, tig = lane & 3;
    int ra = blockIdx.x * 128 + warp * 16 + gid;
    int rb = ra + 8;
    bool va = ra < M, vb = rb < M;
    const float* Aa = A + (size_t)(va ? ra : 0) * HID;
    const float* Ab = A + (size_t)(vb ? rb : 0) * HID;

    float c[16][4];
    #pragma unroll
    for (int t = 0; t < 16; ++t) { c[t][0] = c[t][1] = c[t][2] = c[t][3] = 0.f; }

    for (int kc = 0; kc < 2; ++kc) {
        int kbase = kc * 64;
        __syncthreads();
        for (int i = threadIdx.x; i < 64 * 128; i += 256) {
            int k = i >> 7, n = i & 127;
            Ws[k * WPAD + n] = f2tf32(W[(size_t)(kbase + k) * HID + n]);
        }
        __syncthreads();
        #pragma unroll
        for (int k8 = 0; k8 < 8; ++k8) {
            int k0 = kbase + k8 * 8;
            int ks = k8 * 8;
            uint32_t a0 = f2tf32(Aa[k0 + tig]);
            uint32_t a1 = f2tf32(Ab[k0 + tig]);
            uint32_t a2 = f2tf32(Aa[k0 + 4 + tig]);
            uint32_t a3 = f2tf32(Ab[k0 + 4 + tig]);
            const uint32_t* b0row = Ws + (ks + tig) * WPAD + gid;
            const uint32_t* b1row = Ws + (ks + 4 + tig) * WPAD + gid;
            #pragma unroll
            for (int t = 0; t < 16; ++t) {
                uint32_t b0 = b0row[t * 8];
                uint32_t b1 = b1row[t * 8];
                asm volatile(
                    "mma.sync.aligned.m16n8k8.row.col.f32.tf32.tf32.f32 "
                    "{%0,%1,%2,%3}, {%4,%5,%6,%7}, {%8,%9}, {%0,%1,%2,%3};"
                    : "+f"(c[t][0]), "+f"(c[t][1]), "+f"(c[t][2]), "+f"(c[t][3])
                    : "r"(a0), "r"(a1), "r"(a2), "r"(a3), "r"(b0), "r"(b1));
            }
        }
    }

    // store projected rows
    #pragma unroll
    for (int t = 0; t < 16; ++t) {
        int col = t * 8 + 2 * tig;
        if (va) *(float2*)(C + (size_t)ra * HID + col) = make_float2(c[t][0], c[t][1]);
        if (vb) *(float2*)(C + (size_t)rb * HID + col) = make_float2(c[t][2], c[t][3]);
    }

    // epilogue: attention logits via quad reduction (lanes of a quad differ only in tig)
    {
        float pa[4] = {0, 0, 0, 0}, pb[4] = {0, 0, 0, 0};
        #pragma unroll
        for (int t = 0; t < 16; ++t) {
            int col = t * 8 + 2 * tig;
            float w0 = avs[col], w1 = avs[col + 1];
            pa[t >> 2] += c[t][0] * w0 + c[t][1] * w1;
            pb[t >> 2] += c[t][2] * w0 + c[t][3] * w1;
        }
        #pragma unroll
        for (int hh = 0; hh < 4; ++hh) {
            pa[hh] += __shfl_xor_sync(~0u, pa[hh], 1);
            pa[hh] += __shfl_xor_sync(~0u, pa[hh], 2);
            pb[hh] += __shfl_xor_sync(~0u, pb[hh], 1);
            pb[hh] += __shfl_xor_sync(~0u, pb[hh], 2);
        }
        if (tig == 0) {
            if (va) ((float4*)als)[ra] = make_float4(pa[0], pa[1], pa[2], pa[3]);
            if (vb) ((float4*)als)[rb] = make_float4(pb[0], pb[1], pb[2], pb[3]);
        }
        if (avd) {
            float qa[4] = {0, 0, 0, 0}, qb[4] = {0, 0, 0, 0};
            #pragma unroll
            for (int t = 0; t < 16; ++t) {
                int col = t * 8 + 2 * tig;
                float w0 = avd[col], w1 = avd[col + 1];
                qa[t >> 2] += c[t][0] * w0 + c[t][1] * w1;
                qb[t >> 2] += c[t][2] * w0 + c[t][3] * w1;
            }
            #pragma unroll
            for (int hh = 0; hh < 4; ++hh) {
                qa[hh] += __shfl_xor_sync(~0u, qa[hh], 1);
                qa[hh] += __shfl_xor_sync(~0u, qa[hh], 2);
                qb[hh] += __shfl_xor_sync(~0u, qb[hh], 1);
                qb[hh] += __shfl_xor_sync(~0u, qb[hh], 2);
            }
            if (tig == 0) {
                if (va) ((float4*)ald)[ra] = make_float4(qa[0], qa[1], qa[2], qa[3]);
                if (vb) ((float4*)ald)[rb] = make_float4(qb[0], qb[1], qb[2], qb[3]);
            }
        }
    }
}

// ---------------- input features ----------------
__global__ void gemm64_kernel(const float* __restrict__ A, const float* __restrict__ W,
                              const float* __restrict__ b, float* __restrict__ C, int M) {
    __shared__ float As[16][64];
    int row0 = blockIdx.x * 16;
    int j = threadIdx.x;
    for (int i = j; i < 16 * 64; i += 128) {
        int r = i >> 6, k = i & 63;
        int m = row0 + r;
        As[r][k] = (m < M) ? A[(size_t)m * 64 + k] : 0.f;
    }
    __syncthreads();
    float acc[16];
    #pragma unroll
    for (int r = 0; r < 16; ++r) acc[r] = 0.f;
    const float4* As4 = (const float4*)&As[0][0];
    #pragma unroll 4
    for (int k4 = 0; k4 < 16; ++k4) {
        int k = k4 * 4;
        float w0 = W[(k + 0) * HID + j];
        float w1 = W[(k + 1) * HID + j];
        float w2 = W[(k + 2) * HID + j];
        float w3 = W[(k + 3) * HID + j];
        #pragma unroll
        for (int r = 0; r < 16; ++r) {
            float4 a = As4[r * 16 + k4];
            acc[r] += a.x * w0;
            acc[r] += a.y * w1;
            acc[r] += a.z * w2;
            acc[r] += a.w * w3;
        }
    }
    float bj = b[j];
    #pragma unroll
    for (int r = 0; r < 16; ++r) {
        int m = row0 + r;
        if (m < M) C[(size_t)m * HID + j] = acc[r] + bj;
    }
}

__global__ void feat_sp_kernel(const int* __restrict__ sp_idx,
                               const float* __restrict__ emb, const float* __restrict__ grp,
                               const float* __restrict__ W, const float* __restrict__ b,
                               float* __restrict__ C) {
    __shared__ float As[16][64];
    int row0 = blockIdx.x * 16;
    int j = threadIdx.x;
    for (int i = j; i < 16 * 64; i += 128) {
        int r = i >> 6, k = i & 63;
        int m = row0 + r;
        float v = 0.f;
        if (m < NSP) {
            if (k < 48) v = emb[(size_t)sp_idx[m] * 48 + k];
            else        v = grp[(size_t)m * 16 + (k - 48)];
        }
        As[r][k] = v;
    }
    __syncthreads();
    float acc[16];
    #pragma unroll
    for (int r = 0; r < 16; ++r) acc[r] = 0.f;
    const float4* As4 = (const float4*)&As[0][0];
    #pragma unroll 4
    for (int k4 = 0; k4 < 16; ++k4) {
        int k = k4 * 4;
        float w0 = W[(k + 0) * HID + j];
        float w1 = W[(k + 1) * HID + j];
        float w2 = W[(k + 2) * HID + j];
        float w3 = W[(k + 3) * HID + j];
        #pragma unroll
        for (int r = 0; r < 16; ++r) {
            float4 a = As4[r * 16 + k4];
            acc[r] += a.x * w0;
            acc[r] += a.y * w1;
            acc[r] += a.z * w2;
            acc[r] += a.w * w3;
        }
    }
    float bj = b[j];
    #pragma unroll
    for (int r = 0; r < 16; ++r) {
        int m = row0 + r;
        if (m < NSP) C[(size_t)m * HID + j] = acc[r] + bj;
    }
}

// ---------------- wd (both layers, rels 0/1) : wd[l][r][h][k] ----------------
__global__ void wd_all_kernel(const float* __restrict__ gatw, const float* __restrict__ gatad,
                              float* __restrict__ wd) {
    int t = blockIdx.x * blockDim.x + threadIdx.x;
    if (t >= 2048) return;
    int l = t >> 10, rem = t & 1023, r = rem >> 9, rem2 = rem & 511, h = rem2 >> 7, k = rem2 & 127;
    const float* W  = gatw  + ((size_t)l * 3 + r) * HID * HID;
    const float* ad = gatad + ((size_t)l * 3 + r) * HID;
    float s = 0.f;
    #pragma unroll
    for (int c = 0; c < 32; ++c) s += W[k * HID + h * CH + c] * ad[h * CH + c];
    wd[t] = s;
}

// ---------------- dst logits for rel0 (sp) + rel1 (loc), one launch ----------------
__global__ void ald_dot2_kernel(const float* __restrict__ hsp, const float* __restrict__ hloc,
                                const float* __restrict__ wdl,   // [2][4][128] for this layer
                                float* __restrict__ ald0, float* __restrict__ ald1) {
    int gw = (blockIdx.x * blockDim.x + threadIdx.x) >> 5;
    int lane = threadIdx.x & 31;
    const float* H; const float* wd; float* ald; int w;
    if (gw < NSP)                { H = hsp;  wd = wdl;       ald = ald0; w = gw; }
    else if (gw < NSP + NLOC)    { H = hloc; wd = wdl + 512; ald = ald1; w = gw - NSP; }
    else return;
    float4 hv = ((const float4*)H)[(size_t)w * 32 + lane];
    float r[4];
    #pragma unroll
    for (int hh = 0; hh < 4; ++hh) {
        float4 wv = ((const float4*)wd)[hh * 32 + lane];
        r[hh] = hv.x * wv.x + hv.y * wv.y + hv.z * wv.z + hv.w * wv.w;
    }
    #pragma unroll
    for (int off = 16; off; off >>= 1) {
        #pragma unroll
        for (int hh = 0; hh < 4; ++hh) r[hh] += __shfl_xor_sync(~0u, r[hh], off);
    }
    if (lane < 4) ald[(size_t)w * 4 + lane] = r[lane];
}

// ---------------- CSR build ----------------
__global__ void fill3_kernel(int* __restrict__ p0, int n0, int* __restrict__ p1, int n1,
                             int* __restrict__ p2, int n2) {
    int i = blockIdx.x * blockDim.x + threadIdx.x;
    if (i < n0) p0[i] = 0;
    if (i < n1) p1[i] = 0;
    if (i < n2) p2[i] = 0;
}

__global__ void count3_kernel(const int* __restrict__ e0, const int* __restrict__ e1,
                              const int* __restrict__ e2,
                              int* __restrict__ d0, int* __restrict__ d1, int* __restrict__ d2) {
    int e = blockIdx.x * blockDim.x + threadIdx.x;
    if (e < EOBS) {
        atomicAdd(&d0[e0[EOBS + e]], 1);
        atomicAdd(&d1[e1[EOBS + e]], 1);
    }
    if (e < ENEAR) atomicAdd(&d2[e2[ENEAR + e]], 1);
}

__device__ void scan_one(const int* __restrict__ deg, int* __restrict__ rowptr,
                         int* __restrict__ cursor, int n, int* sh, int* carry_p) {
    if (threadIdx.x == 0) *carry_p = 0;
    __syncthreads();
    for (int base = 0; base < n; base += 1024) {
        int i = base + (int)threadIdx.x;
        int v = (i < n) ? deg[i] : 0;
        sh[threadIdx.x] = v;
        __syncthreads();
        for (int off = 1; off < 1024; off <<= 1) {
            int t = (threadIdx.x >= (unsigned)off) ? sh[threadIdx.x - off] : 0;
            __syncthreads();
            sh[threadIdx.x] += t;
            __syncthreads();
        }
        int excl = sh[threadIdx.x] - v;
        if (i < n) {
            int o = *carry_p + excl;
            rowptr[i] = o;
            cursor[i] = o;
        }
        __syncthreads();
        if (threadIdx.x == 1023) *carry_p += sh[1023];
        __syncthreads();
    }
    if (threadIdx.x == 0) rowptr[n] = *carry_p;
}

__global__ void scan3_kernel(const int* __restrict__ d0, int* __restrict__ r0, int* __restrict__ c0, int n0,
                             const int* __restrict__ d1, int* __restrict__ r1, int* __restrict__ c1, int n1,
                             const int* __restrict__ d2, int* __restrict__ r2, int* __restrict__ c2, int n2) {
    __shared__ int sh[1024];
    __shared__ int carry;
    if (blockIdx.x == 0)      scan_one(d0, r0, c0, n0, sh, &carry);
    else if (blockIdx.x == 1) scan_one(d1, r1, c1, n1, sh, &carry);
    else                      scan_one(d2, r2, c2, n2, sh, &carry);
}

__global__ void scatter3_kernel(const int* __restrict__ e0, const int* __restrict__ e1,
                                const int* __restrict__ e2,
                                int* __restrict__ cu0, int* __restrict__ cu1, int* __restrict__ cu2,
                                int* __restrict__ cs0, int* __restrict__ cs1, int* __restrict__ cs2) {
    int e = blockIdx.x * blockDim.x + threadIdx.x;
    if (e < EOBS) {
        int d = e0[EOBS + e];
        cs0[atomicAdd(&cu0[d], 1)] = e0[e];
        d = e1[EOBS + e];
        cs1[atomicAdd(&cu1[d], 1)] = e1[e];
    }
    if (e < ENEAR) {
        int d = e2[ENEAR + e];
        cs2[atomicAdd(&cu2[d], 1)] = e2[e];
    }
}

// ---------------- fused softmax + aggregate + residual + bias (+relu) ----------------
__device__ __forceinline__ float4 gather_rel(const int* __restrict__ rp, const int* __restrict__ cs,
                                             const float* __restrict__ als, float ad,
                                             const float* __restrict__ P,
                                             int w, int lane, int h, bool self) {
    float den = 0.f, ax = 0.f, ay = 0.f, az = 0.f, aw = 0.f;
    if (self) {
        float q = __expf(lrelu(__ldg(als + (size_t)w * 4 + h) + ad));
        den = q;
        float4 x = __ldg((const float4*)P + (size_t)w * 32 + lane);
        ax = q * x.x; ay = q * x.y; az = q * x.z; aw = q * x.w;
    }
    int i = __ldg(rp + w), end = __ldg(rp + w + 1);
    for (; i + 4 <= end; i += 4) {
        int s0 = __ldg(cs + i + 0);
        int s1 = __ldg(cs + i + 1);
        int s2 = __ldg(cs + i + 2);
        int s3 = __ldg(cs + i + 3);
        float e0 = lrelu(__ldg(als + (size_t)s0 * 4 + h) + ad);
        float e1 = lrelu(__ldg(als + (size_t)s1 * 4 + h) + ad);
        float e2 = lrelu(__ldg(als + (size_t)s2 * 4 + h) + ad);
        float e3 = lrelu(__ldg(als + (size_t)s3 * 4 + h) + ad);
        float4 x0 = __ldg((const float4*)P + (size_t)s0 * 32 + lane);
        float4 x1 = __ldg((const float4*)P + (size_t)s1 * 32 + lane);
        float4 x2 = __ldg((const float4*)P + (size_t)s2 * 32 + lane);
        float4 x3 = __ldg((const float4*)P + (size_t)s3 * 32 + lane);
        float q0 = __expf(e0), q1 = __expf(e1), q2 = __expf(e2), q3 = __expf(e3);
        den += q0 + q1 + q2 + q3;
        ax += q0 * x0.x + q1 * x1.x + q2 * x2.x + q3 * x3.x;
        ay += q0 * x0.y + q1 * x1.y + q2 * x2.y + q3 * x3.y;
        az += q0 * x0.z + q1 * x1.z + q2 * x2.z + q3 * x3.z;
        aw += q0 * x0.w + q1 * x1.w + q2 * x2.w + q3 * x3.w;
    }
    for (; i < end; ++i) {
        int s = __ldg(cs + i);
        float q = __expf(lrelu(__ldg(als + (size_t)s * 4 + h) + ad));
        float4 x = __ldg((const float4*)P + (size_t)s * 32 + lane);
        den += q;
        ax += q * x.x; ay += q * x.y; az += q * x.z; aw += q * x.w;
    }
    float inv = 1.f / (den + 1e-16f);
    return make_float4(ax * inv, ay * inv, az * inv, aw * inv);
}

__global__ void aggr_fused_kernel(const int* __restrict__ rp_obs, const int* __restrict__ cs_obs,
                                  const int* __restrict__ rp_obsat, const int* __restrict__ cs_obsat,
                                  const int* __restrict__ rp_near, const int* __restrict__ cs_near,
                                  const float* __restrict__ als0, const float* __restrict__ ald0,
                                  const float* __restrict__ als1, const float* __restrict__ ald1,
                                  const float* __restrict__ als2, const float* __restrict__ ald2,
                                  const float* __restrict__ PlocA, const float* __restrict__ PspB,
                                  const float* __restrict__ PlocC,
                                  const float* __restrict__ hsp, const float* __restrict__ hloc,
                                  const float* __restrict__ b0, const float* __restrict__ b1,
                                  const float* __restrict__ b2,
                                  float* __restrict__ outsp, float* __restrict__ outloc,
                                  int do_relu) {
    int gw = (blockIdx.x * blockDim.x + threadIdx.x) >> 5;
    int lane = threadIdx.x & 31;
    int h = lane >> 3;
    if (gw < NSP) {
        int w = gw;
        float4 m = gather_rel(rp_obs, cs_obs, als0,
                              __ldg(ald0 + (size_t)w * 4 + h), PlocA, w, lane, h, false);
        float4 hh = __ldg((const float4*)hsp + (size_t)w * 32 + lane);
        float4 bb = __ldg((const float4*)b0 + lane);
        float4 o = make_float4(hh.x + bb.x + m.x, hh.y + bb.y + m.y,
                               hh.z + bb.z + m.z, hh.w + bb.w + m.w);
        if (do_relu) {
            o.x = fmaxf(o.x, 0.f); o.y = fmaxf(o.y, 0.f);
            o.z = fmaxf(o.z, 0.f); o.w = fmaxf(o.w, 0.f);
        }
        ((float4*)outsp)[(size_t)w * 32 + lane] = o;
    } else if (gw < NSP + NLOC) {
        int w = gw - NSP;
        float4 m1 = gather_rel(rp_obsat, cs_obsat, als1,
                               __ldg(ald1 + (size_t)w * 4 + h), PspB, w, lane, h, false);
        float4 m2 = gather_rel(rp_near, cs_near, als2,
                               __ldg(ald2 + (size_t)w * 4 + h), PlocC, w, lane, h, true);
        float4 hh = ((const float4*)hloc)[(size_t)w * 32 + lane];
        float4 bb1 = __ldg((const float4*)b1 + lane);
        float4 bb2 = __ldg((const float4*)b2 + lane);
        float4 o = make_float4(hh.x + bb1.x + bb2.x + m1.x + m2.x,
                               hh.y + bb1.y + bb2.y + m1.y + m2.y,
                               hh.z + bb1.z + bb2.z + m1.z + m2.z,
                               hh.w + bb1.w + bb2.w + m1.w + m2.w);
        if (do_relu) {
            o.x = fmaxf(o.x, 0.f); o.y = fmaxf(o.y, 0.f);
            o.z = fmaxf(o.z, 0.f); o.w = fmaxf(o.w, 0.f);
        }
        ((float4*)outloc)[(size_t)w * 32 + lane] = o;
    }
}

// ---------------- host ----------------
static float* symaddrf(const void* sym) { void* p = nullptr; cudaGetSymbolAddress(&p, sym); return (float*)p; }
static int*   symaddri(const void* sym) { void* p = nullptr; cudaGetSymbolAddress(&p, sym); return (int*)p; }

extern "C" void kernel_launch(void* const* d_in, const int* in_sizes, int n_in,
                              void* d_out, int out_size) {
    const int*   sp_idx = (const int*)  d_in[0];
    const float* grp    = (const float*)d_in[1];
    const float* locx   = (const float*)d_in[2];
    const int*   ei_obs   = (const int*)d_in[3];
    const int*   ei_obsat = (const int*)d_in[4];
    const int*   ei_near  = (const int*)d_in[5];
    const float* emb    = (const float*)d_in[6];
    const float* spw    = (const float*)d_in[7];
    const float* spb    = (const float*)d_in[8];
    const float* locw   = (const float*)d_in[9];
    const float* locb   = (const float*)d_in[10];
    const float* gatw   = (const float*)d_in[11];
    const float* gatas  = (const float*)d_in[12];
    const float* gatad  = (const float*)d_in[13];
    const float* gatb   = (const float*)d_in[14];
    float* out = (float*)d_out;

    float* hsp   = symaddrf(g_hsp);
    float* hloc  = symaddrf(g_hloc);
    float* PlocA = symaddrf(g_PlocA);
    float* PlocC = symaddrf(g_PlocC);
    float* PspB  = symaddrf(g_PspB);
    float* als0  = symaddrf(g_als0);
    float* ald0  = symaddrf(g_ald0);
    float* als1  = symaddrf(g_als1);
    float* ald1  = symaddrf(g_ald1);
    float* als2  = symaddrf(g_als2);
    float* ald2  = symaddrf(g_ald2);
    float* wd    = symaddrf(g_wd);

    int* rp_obs   = symaddri(g_rp_obs);
    int* rp_obsat = symaddri(g_rp_obsat);
    int* rp_near  = symaddri(g_rp_near);
    int* cu_obs   = symaddri(g_cur_obs);
    int* cu_obsat = symaddri(g_cur_obsat);
    int* cu_near  = symaddri(g_cur_near);
    int* dg_obs   = symaddri(g_deg_obs);
    int* dg_obsat = symaddri(g_deg_obsat);
    int* dg_near  = symaddri(g_deg_near);
    int* cs_obs   = symaddri(g_csrc_obs);
    int* cs_obsat = symaddri(g_csrc_obsat);
    int* cs_near  = symaddri(g_csrc_near);

    // CSR build (one pass set, reused both layers)
    fill3_kernel<<<(NLOC + 255) / 256, 256>>>(dg_obs, NSP, dg_obsat, NLOC, dg_near, NLOC);
    count3_kernel<<<(EOBS + 255) / 256, 256>>>(ei_obs, ei_obsat, ei_near,
                                               dg_obs, dg_obsat, dg_near);
    scan3_kernel<<<3, 1024>>>(dg_obs, rp_obs, cu_obs, NSP,
                              dg_obsat, rp_obsat, cu_obsat, NLOC,
                              dg_near, rp_near, cu_near, NLOC);
    scatter3_kernel<<<(EOBS + 255) / 256, 256>>>(ei_obs, ei_obsat, ei_near,
                                                 cu_obs, cu_obsat, cu_near,
                                                 cs_obs, cs_obsat, cs_near);

    // input features + per-layer dst-fold weights
    feat_sp_kernel<<<(NSP + 15) / 16, 128>>>(sp_idx, emb, grp, spw, spb, hsp);
    gemm64_kernel<<<(NLOC + 15) / 16, 128>>>(locx, locw, locb, hloc, NLOC);
    wd_all_kernel<<<8, 256>>>(gatw, gatad, wd);

    int aggr_blocks = ((NSP + NLOC) * 32 + 255) / 256;

    for (int l = 0; l < 2; ++l) {
        const float* Wl  = gatw  + (size_t)l * 3 * HID * HID;
        const float* asl = gatas + (size_t)l * 3 * HID;
        const float* ad2 = gatad + (size_t)l * 3 * HID + 2 * HID;
        const float* b0  = gatb  + (size_t)l * 3 * HID;
        const float* b1  = b0 + HID;
        const float* b2  = b0 + 2 * HID;
        const float* wdl = wd + (size_t)l * 1024;

        // projections + src logits (+ nearby dst logits) in one launch
        dim3 ggrid((NLOC + 127) / 128, 1, 3);
        gemm_tc_fused<<<ggrid, 256>>>(hsp, hloc, Wl, asl, ad2,
                                      PlocA, PspB, PlocC,
                                      als0, als1, als2, ald2);
        // dst logits for cross-type relations
        ald_dot2_kernel<<<aggr_blocks, 256>>>(hsp, hloc, wdl, ald0, ald1);

        // fused gather+softmax+residual+bias (+relu for layer 0)
        if (l == 0) {
            aggr_fused_kernel<<<aggr_blocks, 256>>>(rp_obs, cs_obs, rp_obsat, cs_obsat,
                                                    rp_near, cs_near,
                                                    als0, ald0, als1, ald1, als2, ald2,
                                                    PlocA, PspB, PlocC, hsp, hloc,
                                                    b0, b1, b2, hsp, hloc, 1);
        } else {
            aggr_fused_kernel<<<aggr_blocks, 256>>>(rp_obs, cs_obs, rp_obsat, cs_obsat,
                                                    rp_near, cs_near,
                                                    als0, ald0, als1, ald1, als2, ald2,
                                                    PlocA, PspB, PlocC, hsp, hloc,
                                                    b0, b1, b2, out, out + (size_t)NSP * HID, 0);
        }
    }
}

// round 9
// speedup vs baseline: 4.5754x; 1.1551x over previous
#include <cuda_runtime.h>
#include <cuda_fp16.h>
#include <math.h>
#include <stdint.h>

#define NSP   10000
#define NLOC  50000
#define EOBS  500000
#define ENEAR 400000
#define HID   128
#define HEADS 4
#define CH    32

// ---------------- scratch (static device globals) ----------------
__device__ float  g_hsp  [NSP  * HID];
__device__ float  g_hloc [NLOC * HID];
__device__ __half g_PlocA[NLOC * HID];
__device__ __half g_PlocC[NLOC * HID];
__device__ __half g_PspB [NSP  * HID];
__device__ float g_als0[NLOC * HEADS];
__device__ float g_ald0[NSP  * HEADS];
__device__ float g_als1[NSP  * HEADS];
__device__ float g_ald1[NLOC * HEADS];
__device__ float g_als2[NLOC * HEADS];
__device__ float g_ald2[NLOC * HEADS];
__device__ float g_wd  [2 * 2 * HEADS * HID];   // [layer][rel(0=obs,1=obsat)][h][k]

// CSR scratch
__device__ int g_rp_obs  [NSP + 1];
__device__ int g_rp_obsat[NLOC + 1];
__device__ int g_rp_near [NLOC + 1];
__device__ int g_cur_obs  [NSP];
__device__ int g_cur_obsat[NLOC];
__device__ int g_cur_near [NLOC];
__device__ int g_deg_obs  [NSP];
__device__ int g_deg_obsat[NLOC];
__device__ int g_deg_near [NLOC];
__device__ int g_csrc_obs  [EOBS];
__device__ int g_csrc_obsat[EOBS];
__device__ int g_csrc_near [ENEAR];

__device__ __forceinline__ float lrelu(float x) { return x > 0.f ? x : 0.2f * x; }

__device__ __forceinline__ uint32_t f2tf32(float f) {
    uint32_t r;
    asm("cvt.rna.tf32.f32 %0, %1;" : "=r"(r) : "f"(f));
    return r;
}

// ---------------- tf32 GEMM + attention-logit epilogue; P stored as fp16 ----------------
#define WPAD 136
__global__ void __launch_bounds__(256)
gemm_tc_fused(const float* __restrict__ hsp, const float* __restrict__ hloc,
              const float* __restrict__ Wbase, const float* __restrict__ asbase,
              const float* __restrict__ ad2,
              __half* __restrict__ PlocA, __half* __restrict__ PspB, __half* __restrict__ PlocC,
              float* __restrict__ als0, float* __restrict__ als1,
              float* __restrict__ als2, float* __restrict__ ald2o) {
    int rel = blockIdx.z;
    const float* A;  const float* W;  const float* avs;  const float* avd = nullptr;
    __half* C;  float* als;  float* ald = nullptr;  int M;
    if (rel == 0)      { A = hloc; W = Wbase;                C = PlocA; M = NLOC; avs = asbase;           als = als0; }
    else if (rel == 1) { A = hsp;  W = Wbase + HID * HID;    C = PspB;  M = NSP;  avs = asbase + HID;     als = als1; }
    else               { A = hloc; W = Wbase + 2 * HID * HID;C = PlocC; M = NLOC; avs = asbase + 2 * HID; als = als2;
                         avd = ad2; ald = ald2o; }
    if (blockIdx.x * 128 >= M) return;

    __shared__ uint32_t Ws[64 * WPAD];
    int warp = threadIdx.x >> 5, lane = threadIdx.x & 31;
    int gid = lane >> 2, tig = lane & 3;
    int ra = blockIdx.x * 128 + warp * 16 + gid;
    int rb = ra + 8;
    bool va = ra < M, vb = rb < M;
    const float* Aa = A + (size_t)(va ? ra : 0) * HID;
    const float* Ab = A + (size_t)(vb ? rb : 0) * HID;

    float c[16][4];
    #pragma unroll
    for (int t = 0; t < 16; ++t) { c[t][0] = c[t][1] = c[t][2] = c[t][3] = 0.f; }

    for (int kc = 0; kc < 2; ++kc) {
        int kbase = kc * 64;
        __syncthreads();
        for (int i = threadIdx.x; i < 64 * 128; i += 256) {
            int k = i >> 7, n = i & 127;
            Ws[k * WPAD + n] = f2tf32(W[(size_t)(kbase + k) * HID + n]);
        }
        __syncthreads();
        #pragma unroll
        for (int k8 = 0; k8 < 8; ++k8) {
            int k0 = kbase + k8 * 8;
            int ks = k8 * 8;
            uint32_t a0 = f2tf32(Aa[k0 + tig]);
            uint32_t a1 = f2tf32(Ab[k0 + tig]);
            uint32_t a2 = f2tf32(Aa[k0 + 4 + tig]);
            uint32_t a3 = f2tf32(Ab[k0 + 4 + tig]);
            const uint32_t* b0row = Ws + (ks + tig) * WPAD + gid;
            const uint32_t* b1row = Ws + (ks + 4 + tig) * WPAD + gid;
            #pragma unroll
            for (int t = 0; t < 16; ++t) {
                uint32_t b0 = b0row[t * 8];
                uint32_t b1 = b1row[t * 8];
                asm volatile(
                    "mma.sync.aligned.m16n8k8.row.col.f32.tf32.tf32.f32 "
                    "{%0,%1,%2,%3}, {%4,%5,%6,%7}, {%8,%9}, {%0,%1,%2,%3};"
                    : "+f"(c[t][0]), "+f"(c[t][1]), "+f"(c[t][2]), "+f"(c[t][3])
                    : "r"(a0), "r"(a1), "r"(a2), "r"(a3), "r"(b0), "r"(b1));
            }
        }
    }

    // store projected rows as fp16
    #pragma unroll
    for (int t = 0; t < 16; ++t) {
        int col = t * 8 + 2 * tig;
        if (va) *(__half2*)(C + (size_t)ra * HID + col) =
            __floats2half2_rn(c[t][0], c[t][1]);
        if (vb) *(__half2*)(C + (size_t)rb * HID + col) =
            __floats2half2_rn(c[t][2], c[t][3]);
    }

    // epilogue: attention logits via quad reduction (fp32 accumulators)
    {
        float pa[4] = {0, 0, 0, 0}, pb[4] = {0, 0, 0, 0};
        #pragma unroll
        for (int t = 0; t < 16; ++t) {
            int col = t * 8 + 2 * tig;
            float w0 = avs[col], w1 = avs[col + 1];
            pa[t >> 2] += c[t][0] * w0 + c[t][1] * w1;
            pb[t >> 2] += c[t][2] * w0 + c[t][3] * w1;
        }
        #pragma unroll
        for (int hh = 0; hh < 4; ++hh) {
            pa[hh] += __shfl_xor_sync(~0u, pa[hh], 1);
            pa[hh] += __shfl_xor_sync(~0u, pa[hh], 2);
            pb[hh] += __shfl_xor_sync(~0u, pb[hh], 1);
            pb[hh] += __shfl_xor_sync(~0u, pb[hh], 2);
        }
        if (tig == 0) {
            if (va) ((float4*)als)[ra] = make_float4(pa[0], pa[1], pa[2], pa[3]);
            if (vb) ((float4*)als)[rb] = make_float4(pb[0], pb[1], pb[2], pb[3]);
        }
        if (avd) {
            float qa[4] = {0, 0, 0, 0}, qb[4] = {0, 0, 0, 0};
            #pragma unroll
            for (int t = 0; t < 16; ++t) {
                int col = t * 8 + 2 * tig;
                float w0 = avd[col], w1 = avd[col + 1];
                qa[t >> 2] += c[t][0] * w0 + c[t][1] * w1;
                qb[t >> 2] += c[t][2] * w0 + c[t][3] * w1;
            }
            #pragma unroll
            for (int hh = 0; hh < 4; ++hh) {
                qa[hh] += __shfl_xor_sync(~0u, qa[hh], 1);
                qa[hh] += __shfl_xor_sync(~0u, qa[hh], 2);
                qb[hh] += __shfl_xor_sync(~0u, qb[hh], 1);
                qb[hh] += __shfl_xor_sync(~0u, qb[hh], 2);
            }
            if (tig == 0) {
                if (va) ((float4*)ald)[ra] = make_float4(qa[0], qa[1], qa[2], qa[3]);
                if (vb) ((float4*)ald)[rb] = make_float4(qb[0], qb[1], qb[2], qb[3]);
            }
        }
    }
}

// ---------------- input features ----------------
__global__ void gemm64_kernel(const float* __restrict__ A, const float* __restrict__ W,
                              const float* __restrict__ b, float* __restrict__ C, int M) {
    __shared__ float As[16][64];
    int row0 = blockIdx.x * 16;
    int j = threadIdx.x;
    for (int i = j; i < 16 * 64; i += 128) {
        int r = i >> 6, k = i & 63;
        int m = row0 + r;
        As[r][k] = (m < M) ? A[(size_t)m * 64 + k] : 0.f;
    }
    __syncthreads();
    float acc[16];
    #pragma unroll
    for (int r = 0; r < 16; ++r) acc[r] = 0.f;
    const float4* As4 = (const float4*)&As[0][0];
    #pragma unroll 4
    for (int k4 = 0; k4 < 16; ++k4) {
        int k = k4 * 4;
        float w0 = W[(k + 0) * HID + j];
        float w1 = W[(k + 1) * HID + j];
        float w2 = W[(k + 2) * HID + j];
        float w3 = W[(k + 3) * HID + j];
        #pragma unroll
        for (int r = 0; r < 16; ++r) {
            float4 a = As4[r * 16 + k4];
            acc[r] += a.x * w0;
            acc[r] += a.y * w1;
            acc[r] += a.z * w2;
            acc[r] += a.w * w3;
        }
    }
    float bj = b[j];
    #pragma unroll
    for (int r = 0; r < 16; ++r) {
        int m = row0 + r;
        if (m < M) C[(size_t)m * HID + j] = acc[r] + bj;
    }
}

__global__ void feat_sp_kernel(const int* __restrict__ sp_idx,
                               const float* __restrict__ emb, const float* __restrict__ grp,
                               const float* __restrict__ W, const float* __restrict__ b,
                               float* __restrict__ C) {
    __shared__ float As[16][64];
    int row0 = blockIdx.x * 16;
    int j = threadIdx.x;
    for (int i = j; i < 16 * 64; i += 128) {
        int r = i >> 6, k = i & 63;
        int m = row0 + r;
        float v = 0.f;
        if (m < NSP) {
            if (k < 48) v = emb[(size_t)sp_idx[m] * 48 + k];
            else        v = grp[(size_t)m * 16 + (k - 48)];
        }
        As[r][k] = v;
    }
    __syncthreads();
    float acc[16];
    #pragma unroll
    for (int r = 0; r < 16; ++r) acc[r] = 0.f;
    const float4* As4 = (const float4*)&As[0][0];
    #pragma unroll 4
    for (int k4 = 0; k4 < 16; ++k4) {
        int k = k4 * 4;
        float w0 = W[(k + 0) * HID + j];
        float w1 = W[(k + 1) * HID + j];
        float w2 = W[(k + 2) * HID + j];
        float w3 = W[(k + 3) * HID + j];
        #pragma unroll
        for (int r = 0; r < 16; ++r) {
            float4 a = As4[r * 16 + k4];
            acc[r] += a.x * w0;
            acc[r] += a.y * w1;
            acc[r] += a.z * w2;
            acc[r] += a.w * w3;
        }
    }
    float bj = b[j];
    #pragma unroll
    for (int r = 0; r < 16; ++r) {
        int m = row0 + r;
        if (m < NSP) C[(size_t)m * HID + j] = acc[r] + bj;
    }
}

// ---------------- wd (both layers, rels 0/1) ----------------
__global__ void wd_all_kernel(const float* __restrict__ gatw, const float* __restrict__ gatad,
                              float* __restrict__ wd) {
    int t = blockIdx.x * blockDim.x + threadIdx.x;
    if (t >= 2048) return;
    int l = t >> 10, rem = t & 1023, r = rem >> 9, rem2 = rem & 511, h = rem2 >> 7, k = rem2 & 127;
    const float* W  = gatw  + ((size_t)l * 3 + r) * HID * HID;
    const float* ad = gatad + ((size_t)l * 3 + r) * HID;
    float s = 0.f;
    #pragma unroll
    for (int c = 0; c < 32; ++c) s += W[k * HID + h * CH + c] * ad[h * CH + c];
    wd[t] = s;
}

// ---------------- dst logits (layer 0 only; layer 1 fused into aggr epilogue) ----------------
__global__ void ald_dot2_kernel(const float* __restrict__ hsp, const float* __restrict__ hloc,
                                const float* __restrict__ wdl,
                                float* __restrict__ ald0, float* __restrict__ ald1) {
    int gw = (blockIdx.x * blockDim.x + threadIdx.x) >> 5;
    int lane = threadIdx.x & 31;
    const float* H; const float* wd; float* ald; int w;
    if (gw < NSP)                { H = hsp;  wd = wdl;       ald = ald0; w = gw; }
    else if (gw < NSP + NLOC)    { H = hloc; wd = wdl + 512; ald = ald1; w = gw - NSP; }
    else return;
    float4 hv = ((const float4*)H)[(size_t)w * 32 + lane];
    float r[4];
    #pragma unroll
    for (int hh = 0; hh < 4; ++hh) {
        float4 wv = ((const float4*)wd)[hh * 32 + lane];
        r[hh] = hv.x * wv.x + hv.y * wv.y + hv.z * wv.z + hv.w * wv.w;
    }
    #pragma unroll
    for (int off = 16; off; off >>= 1) {
        #pragma unroll
        for (int hh = 0; hh < 4; ++hh) r[hh] += __shfl_xor_sync(~0u, r[hh], off);
    }
    if (lane < 4) ald[(size_t)w * 4 + lane] = r[lane];
}

// ---------------- CSR build ----------------
__global__ void fill3_kernel(int* __restrict__ p0, int n0, int* __restrict__ p1, int n1,
                             int* __restrict__ p2, int n2) {
    int i = blockIdx.x * blockDim.x + threadIdx.x;
    if (i < n0) p0[i] = 0;
    if (i < n1) p1[i] = 0;
    if (i < n2) p2[i] = 0;
}

__global__ void count3_kernel(const int* __restrict__ e0, const int* __restrict__ e1,
                              const int* __restrict__ e2,
                              int* __restrict__ d0, int* __restrict__ d1, int* __restrict__ d2) {
    int e = blockIdx.x * blockDim.x + threadIdx.x;
    if (e < EOBS) {
        atomicAdd(&d0[e0[EOBS + e]], 1);
        atomicAdd(&d1[e1[EOBS + e]], 1);
    }
    if (e < ENEAR) atomicAdd(&d2[e2[ENEAR + e]], 1);
}

// warp-shuffle scan: 1024 threads, 4 syncs per 1024-chunk
__device__ void scan_one(const int* __restrict__ deg, int* __restrict__ rowptr,
                         int* __restrict__ cursor, int n, int* warpsums, int* carry_p) {
    int lane = threadIdx.x & 31, wid = threadIdx.x >> 5;
    if (threadIdx.x == 0) *carry_p = 0;
    __syncthreads();
    for (int base = 0; base < n; base += 1024) {
        int i = base + (int)threadIdx.x;
        int v = (i < n) ? deg[i] : 0;
        int x = v;
        #pragma unroll
        for (int off = 1; off < 32; off <<= 1) {
            int t = __shfl_up_sync(~0u, x, off);
            if (lane >= off) x += t;
        }
        if (lane == 31) warpsums[wid] = x;
        __syncthreads();
        if (wid == 0) {
            int s = warpsums[lane];
            #pragma unroll
            for (int off = 1; off < 32; off <<= 1) {
                int t = __shfl_up_sync(~0u, s, off);
                if (lane >= off) s += t;
            }
            warpsums[lane] = s;
        }
        __syncthreads();
        int warpoff = wid ? warpsums[wid - 1] : 0;
        int excl = x - v + warpoff;
        int carry = *carry_p;
        if (i < n) {
            int o = carry + excl;
            rowptr[i] = o;
            cursor[i] = o;
        }
        __syncthreads();
        if (threadIdx.x == 0) *carry_p = carry + warpsums[31];
        __syncthreads();
    }
    if (threadIdx.x == 0) rowptr[n] = *carry_p;
}

__global__ void scan3_kernel(const int* __restrict__ d0, int* __restrict__ r0, int* __restrict__ c0, int n0,
                             const int* __restrict__ d1, int* __restrict__ r1, int* __restrict__ c1, int n1,
                             const int* __restrict__ d2, int* __restrict__ r2, int* __restrict__ c2, int n2) {
    __shared__ int warpsums[32];
    __shared__ int carry;
    if (blockIdx.x == 0)      scan_one(d0, r0, c0, n0, warpsums, &carry);
    else if (blockIdx.x == 1) scan_one(d1, r1, c1, n1, warpsums, &carry);
    else                      scan_one(d2, r2, c2, n2, warpsums, &carry);
}

__global__ void scatter3_kernel(const int* __restrict__ e0, const int* __restrict__ e1,
                                const int* __restrict__ e2,
                                int* __restrict__ cu0, int* __restrict__ cu1, int* __restrict__ cu2,
                                int* __restrict__ cs0, int* __restrict__ cs1, int* __restrict__ cs2) {
    int e = blockIdx.x * blockDim.x + threadIdx.x;
    if (e < EOBS) {
        int d = e0[EOBS + e];
        cs0[atomicAdd(&cu0[d], 1)] = e0[e];
        d = e1[EOBS + e];
        cs1[atomicAdd(&cu1[d], 1)] = e1[e];
    }
    if (e < ENEAR) {
        int d = e2[ENEAR + e];
        cs2[atomicAdd(&cu2[d], 1)] = e2[e];
    }
}

// ---------------- fused softmax + aggregate + residual + bias (+relu) ----------------
__device__ __forceinline__ void acc_edge(float q, uint2 raw,
                                         float& den, float& ax, float& ay, float& az, float& aw) {
    float2 f01 = __half22float2(*(__half2*)&raw.x);
    float2 f23 = __half22float2(*(__half2*)&raw.y);
    den += q;
    ax += q * f01.x; ay += q * f01.y; az += q * f23.x; aw += q * f23.y;
}

__device__ __forceinline__ float4 gather_rel(const int* __restrict__ rp, const int* __restrict__ cs,
                                             const float* __restrict__ als, float ad,
                                             const __half* __restrict__ P,
                                             int w, int lane, int h, bool self) {
    const uint2* P2 = (const uint2*)P;
    float den = 0.f, ax = 0.f, ay = 0.f, az = 0.f, aw = 0.f;
    if (self) {
        float q = __expf(lrelu(__ldg(als + (size_t)w * 4 + h) + ad));
        uint2 raw = __ldg(P2 + (size_t)w * 32 + lane);
        acc_edge(q, raw, den, ax, ay, az, aw);
    }
    int i = __ldg(rp + w), end = __ldg(rp + w + 1);
    for (; i + 4 <= end; i += 4) {
        int s0 = __ldg(cs + i + 0);
        int s1 = __ldg(cs + i + 1);
        int s2 = __ldg(cs + i + 2);
        int s3 = __ldg(cs + i + 3);
        float e0 = lrelu(__ldg(als + (size_t)s0 * 4 + h) + ad);
        float e1 = lrelu(__ldg(als + (size_t)s1 * 4 + h) + ad);
        float e2 = lrelu(__ldg(als + (size_t)s2 * 4 + h) + ad);
        float e3 = lrelu(__ldg(als + (size_t)s3 * 4 + h) + ad);
        uint2 r0 = __ldg(P2 + (size_t)s0 * 32 + lane);
        uint2 r1 = __ldg(P2 + (size_t)s1 * 32 + lane);
        uint2 r2 = __ldg(P2 + (size_t)s2 * 32 + lane);
        uint2 r3 = __ldg(P2 + (size_t)s3 * 32 + lane);
        acc_edge(__expf(e0), r0, den, ax, ay, az, aw);
        acc_edge(__expf(e1), r1, den, ax, ay, az, aw);
        acc_edge(__expf(e2), r2, den, ax, ay, az, aw);
        acc_edge(__expf(e3), r3, den, ax, ay, az, aw);
    }
    for (; i < end; ++i) {
        int s = __ldg(cs + i);
        float q = __expf(lrelu(__ldg(als + (size_t)s * 4 + h) + ad));
        uint2 raw = __ldg(P2 + (size_t)s * 32 + lane);
        acc_edge(q, raw, den, ax, ay, az, aw);
    }
    float inv = 1.f / (den + 1e-16f);
    return make_float4(ax * inv, ay * inv, az * inv, aw * inv);
}

// wdn != nullptr: also compute NEXT layer's dst logits from the output row (in registers)
__global__ void aggr_fused_kernel(const int* __restrict__ rp_obs, const int* __restrict__ cs_obs,
                                  const int* __restrict__ rp_obsat, const int* __restrict__ cs_obsat,
                                  const int* __restrict__ rp_near, const int* __restrict__ cs_near,
                                  const float* __restrict__ als0, const float* __restrict__ ald0,
                                  const float* __restrict__ als1, const float* __restrict__ ald1,
                                  const float* __restrict__ als2, const float* __restrict__ ald2,
                                  const __half* __restrict__ PlocA, const __half* __restrict__ PspB,
                                  const __half* __restrict__ PlocC,
                                  const float* __restrict__ hsp, const float* __restrict__ hloc,
                                  const float* __restrict__ b0, const float* __restrict__ b1,
                                  const float* __restrict__ b2,
                                  float* __restrict__ outsp, float* __restrict__ outloc,
                                  int do_relu,
                                  const float* __restrict__ wdn,
                                  float* __restrict__ ald0n, float* __restrict__ ald1n) {
    int gw = (blockIdx.x * blockDim.x + threadIdx.x) >> 5;
    int lane = threadIdx.x & 31;
    int h = lane >> 3;
    float4 o;
    const float* wdsel;
    float* aldout;
    int w;
    if (gw < NSP) {
        w = gw;
        float4 m = gather_rel(rp_obs, cs_obs, als0,
                              __ldg(ald0 + (size_t)w * 4 + h), PlocA, w, lane, h, false);
        float4 hh = __ldg((const float4*)hsp + (size_t)w * 32 + lane);
        float4 bb = __ldg((const float4*)b0 + lane);
        o = make_float4(hh.x + bb.x + m.x, hh.y + bb.y + m.y,
                        hh.z + bb.z + m.z, hh.w + bb.w + m.w);
        if (do_relu) {
            o.x = fmaxf(o.x, 0.f); o.y = fmaxf(o.y, 0.f);
            o.z = fmaxf(o.z, 0.f); o.w = fmaxf(o.w, 0.f);
        }
        ((float4*)outsp)[(size_t)w * 32 + lane] = o;
        wdsel = wdn; aldout = ald0n;
    } else if (gw < NSP + NLOC) {
        w = gw - NSP;
        float4 m1 = gather_rel(rp_obsat, cs_obsat, als1,
                               __ldg(ald1 + (size_t)w * 4 + h), PspB, w, lane, h, false);
        float4 m2 = gather_rel(rp_near, cs_near, als2,
                               __ldg(ald2 + (size_t)w * 4 + h), PlocC, w, lane, h, true);
        float4 hh = ((const float4*)hloc)[(size_t)w * 32 + lane];
        float4 bb1 = __ldg((const float4*)b1 + lane);
        float4 bb2 = __ldg((const float4*)b2 + lane);
        o = make_float4(hh.x + bb1.x + bb2.x + m1.x + m2.x,
                        hh.y + bb1.y + bb2.y + m1.y + m2.y,
                        hh.z + bb1.z + bb2.z + m1.z + m2.z,
                        hh.w + bb1.w + bb2.w + m1.w + m2.w);
        if (do_relu) {
            o.x = fmaxf(o.x, 0.f); o.y = fmaxf(o.y, 0.f);
            o.z = fmaxf(o.z, 0.f); o.w = fmaxf(o.w, 0.f);
        }
        ((float4*)outloc)[(size_t)w * 32 + lane] = o;
        wdsel = wdn ? wdn + 512 : nullptr; aldout = ald1n;
    } else return;

    if (wdn) {   // next-layer dst logits from o (registers), no h re-read
        float r[4];
        #pragma unroll
        for (int hh = 0; hh < 4; ++hh) {
            float4 wv = __ldg((const float4*)wdsel + hh * 32 + lane);
            r[hh] = o.x * wv.x + o.y * wv.y + o.z * wv.z + o.w * wv.w;
        }
        #pragma unroll
        for (int off = 16; off; off >>= 1) {
            #pragma unroll
            for (int hh = 0; hh < 4; ++hh) r[hh] += __shfl_xor_sync(~0u, r[hh], off);
        }
        if (lane < 4) aldout[(size_t)w * 4 + lane] = r[lane];
    }
}

// ---------------- host ----------------
static float* symaddrf(const void* sym) { void* p = nullptr; cudaGetSymbolAddress(&p, sym); return (float*)p; }
static __half* symaddrh(const void* sym) { void* p = nullptr; cudaGetSymbolAddress(&p, sym); return (__half*)p; }
static int*   symaddri(const void* sym) { void* p = nullptr; cudaGetSymbolAddress(&p, sym); return (int*)p; }

extern "C" void kernel_launch(void* const* d_in, const int* in_sizes, int n_in,
                              void* d_out, int out_size) {
    const int*   sp_idx = (const int*)  d_in[0];
    const float* grp    = (const float*)d_in[1];
    const float* locx   = (const float*)d_in[2];
    const int*   ei_obs   = (const int*)d_in[3];
    const int*   ei_obsat = (const int*)d_in[4];
    const int*   ei_near  = (const int*)d_in[5];
    const float* emb    = (const float*)d_in[6];
    const float* spw    = (const float*)d_in[7];
    const float* spb    = (const float*)d_in[8];
    const float* locw   = (const float*)d_in[9];
    const float* locb   = (const float*)d_in[10];
    const float* gatw   = (const float*)d_in[11];
    const float* gatas  = (const float*)d_in[12];
    const float* gatad  = (const float*)d_in[13];
    const float* gatb   = (const float*)d_in[14];
    float* out = (float*)d_out;

    float*  hsp   = symaddrf(g_hsp);
    float*  hloc  = symaddrf(g_hloc);
    __half* PlocA = symaddrh(g_PlocA);
    __half* PlocC = symaddrh(g_PlocC);
    __half* PspB  = symaddrh(g_PspB);
    float* als0  = symaddrf(g_als0);
    float* ald0  = symaddrf(g_ald0);
    float* als1  = symaddrf(g_als1);
    float* ald1  = symaddrf(g_ald1);
    float* als2  = symaddrf(g_als2);
    float* ald2  = symaddrf(g_ald2);
    float* wd    = symaddrf(g_wd);

    int* rp_obs   = symaddri(g_rp_obs);
    int* rp_obsat = symaddri(g_rp_obsat);
    int* rp_near  = symaddri(g_rp_near);
    int* cu_obs   = symaddri(g_cur_obs);
    int* cu_obsat = symaddri(g_cur_obsat);
    int* cu_near  = symaddri(g_cur_near);
    int* dg_obs   = symaddri(g_deg_obs);
    int* dg_obsat = symaddri(g_deg_obsat);
    int* dg_near  = symaddri(g_deg_near);
    int* cs_obs   = symaddri(g_csrc_obs);
    int* cs_obsat = symaddri(g_csrc_obsat);
    int* cs_near  = symaddri(g_csrc_near);

    // CSR build
    fill3_kernel<<<(NLOC + 255) / 256, 256>>>(dg_obs, NSP, dg_obsat, NLOC, dg_near, NLOC);
    count3_kernel<<<(EOBS + 255) / 256, 256>>>(ei_obs, ei_obsat, ei_near,
                                               dg_obs, dg_obsat, dg_near);
    scan3_kernel<<<3, 1024>>>(dg_obs, rp_obs, cu_obs, NSP,
                              dg_obsat, rp_obsat, cu_obsat, NLOC,
                              dg_near, rp_near, cu_near, NLOC);
    scatter3_kernel<<<(EOBS + 255) / 256, 256>>>(ei_obs, ei_obsat, ei_near,
                                                 cu_obs, cu_obsat, cu_near,
                                                 cs_obs, cs_obsat, cs_near);

    // input features + dst-fold weights (both layers)
    feat_sp_kernel<<<(NSP + 15) / 16, 128>>>(sp_idx, emb, grp, spw, spb, hsp);
    gemm64_kernel<<<(NLOC + 15) / 16, 128>>>(locx, locw, locb, hloc, NLOC);
    wd_all_kernel<<<8, 256>>>(gatw, gatad, wd);

    int aggr_blocks = ((NSP + NLOC) * 32 + 255) / 256;

    // layer-0 dst logits (layer-1's are fused into layer-0 aggr epilogue)
    ald_dot2_kernel<<<aggr_blocks, 256>>>(hsp, hloc, wd, ald0, ald1);

    for (int l = 0; l < 2; ++l) {
        const float* Wl  = gatw  + (size_t)l * 3 * HID * HID;
        const float* asl = gatas + (size_t)l * 3 * HID;
        const float* ad2 = gatad + (size_t)l * 3 * HID + 2 * HID;
        const float* b0  = gatb  + (size_t)l * 3 * HID;
        const float* b1  = b0 + HID;
        const float* b2  = b0 + 2 * HID;

        dim3 ggrid((NLOC + 127) / 128, 1, 3);
        gemm_tc_fused<<<ggrid, 256>>>(hsp, hloc, Wl, asl, ad2,
                                      PlocA, PspB, PlocC,
                                      als0, als1, als2, ald2);

        if (l == 0) {
            aggr_fused_kernel<<<aggr_blocks, 256>>>(rp_obs, cs_obs, rp_obsat, cs_obsat,
                                                    rp_near, cs_near,
                                                    als0, ald0, als1, ald1, als2, ald2,
                                                    PlocA, PspB, PlocC, hsp, hloc,
                                                    b0, b1, b2, hsp, hloc, 1,
                                                    wd + 1024, ald0, ald1);
        } else {
            aggr_fused_kernel<<<aggr_blocks, 256>>>(rp_obs, cs_obs, rp_obsat, cs_obsat,
                                                    rp_near, cs_near,
                                                    als0, ald0, als1, ald1, als2, ald2,
                                                    PlocA, PspB, PlocC, hsp, hloc,
                                                    b0, b1, b2, out, out + (size_t)NSP * HID, 0,
                                                    nullptr, nullptr, nullptr);
        }
    }
}